// round 1
// baseline (speedup 1.0000x reference)
#include <cuda_runtime.h>
#include <math.h>

#define HW 65536
#define Bn 2

// ---------------- scratch (static device memory, no allocations) ----------------
__device__ float g_xp[Bn * HW];            // preprocessed input
__device__ float g_h192[Bn * 192 * HW];    // first multi-scale conv output (relu)
__device__ float g_h64[Bn * 64 * HW];      // after 1x1 w_p1
__device__ float g_m192[Bn * 192 * HW];    // mid multi-scale conv output (relu)
__device__ float g_m64[Bn * 64 * HW];      // after 1x1 wbp (pre-BN)
__device__ double g_s1[64], g_s2[64];      // BN sums
__device__ float g_a[64], g_bc[64];        // BN scale/shift
__device__ double g_ym[Bn * 64];           // per (b,c) mean of relu(bn(m))
__device__ float g_y[Bn * 64];             // SE gate

// ---------------- preprocess: gamma blend + bilateral (reflect pad) ----------------
__device__ __forceinline__ float blendf(float v) {
    float g = fminf(fmaxf((v + 1.0f) * 0.5f, 1e-6f), 1.0f);
    return 0.6f * g + 0.4f * g * sqrtf(g);   // (1-a)*g + a*g^1.5
}

__global__ void k_pre(const float* __restrict__ x) {
    int idx = blockIdx.x * blockDim.x + threadIdx.x;
    if (idx >= Bn * HW) return;
    int b = idx >> 16, p = idx & (HW - 1);
    int i = p >> 8, j = p & 255;
    const float* xb = x + b * HW;
    float c = blendf(xb[p]);
    const int   di[13] = {-2,-1,-1,-1, 0, 0, 0, 0, 0, 1, 1, 1, 2};
    const int   dj[13] = { 0,-1, 0, 1,-2,-1, 0, 1, 2,-1, 0, 1, 0};
    const float sw[13] = {0.99920032f,0.99960008f,0.99980002f,0.99960008f,
                          0.99920032f,0.99980002f,1.0f,0.99980002f,0.99920032f,
                          0.99960008f,0.99980002f,0.99960008f,0.99920032f};
    float num = 0.f, den = 0.f;
#pragma unroll
    for (int t = 0; t < 13; t++) {
        int ri = i + di[t]; ri = ri < 0 ? -ri : (ri > 255 ? 510 - ri : ri);
        int rj = j + dj[t]; rj = rj < 0 ? -rj : (rj > 255 ? 510 - rj : rj);
        float sh = blendf(xb[ri * 256 + rj]);
        float d = sh - c;
        float w = sw[t] * expf(-200.0f * d * d);   // sigma_color = 0.05
        num = fmaf(w, sh, num);
        den += w;
    }
    g_xp[idx] = num / den;
}

// ---------------- first convs: 1 -> 64 per branch, relu, write into h192 ----------------
template<int R>
__global__ void k_conv1(const float* __restrict__ w, int brBase) {
    constexpr int K = 2 * R + 1, K2 = K * K, TD = 16 + 2 * R;
    __shared__ float tile[TD * TD];
    int bx = blockIdx.x;
    int tx0 = (bx & 15) * 16, ty0 = (bx >> 4) * 16;
    int b = blockIdx.y >> 6, oc = blockIdx.y & 63;
    int tid = threadIdx.x;
    const float* xp = g_xp + b * HW;
    for (int t = tid; t < TD * TD; t += 256) {
        int yy = ty0 - R + t / TD, xx = tx0 - R + t % TD;
        tile[t] = (yy >= 0 && yy < 256 && xx >= 0 && xx < 256) ? xp[yy * 256 + xx] : 0.f;
    }
    __syncthreads();
    int tyl = tid >> 4, txl = tid & 15;
    float acc = 0.f;
    const float* wp = w + oc * K2;
#pragma unroll
    for (int ky = 0; ky < K; ky++)
#pragma unroll
        for (int kx = 0; kx < K; kx++)
            acc = fmaf(tile[(tyl + ky) * TD + txl + kx], __ldg(&wp[ky * K + kx]), acc);
    g_h192[(size_t)(b * 192 + brBase + oc) * HW + (ty0 + tyl) * 256 + tx0 + txl] = fmaxf(acc, 0.f);
}

// ---------------- 1x1 conv: 192 -> 64 (weights in smem, 64 accumulators/thread) ----------------
__global__ void k_1x1(const float* __restrict__ in, const float* __restrict__ w,
                      float* __restrict__ out) {
    __shared__ float ws[192 * 64];   // ws[ic*64+oc] = w[oc*192+ic]  (48KB exactly)
    int tid = threadIdx.x;
    for (int t = tid; t < 192 * 64; t += 256) {
        int oc = t & 63, ic = t >> 6;
        ws[t] = w[oc * 192 + ic];
    }
    __syncthreads();
    int b = blockIdx.y;
    int p = blockIdx.x * 256 + tid;
    const float* ip = in + (size_t)b * 192 * HW + p;
    float acc[64];
#pragma unroll
    for (int o = 0; o < 64; o++) acc[o] = 0.f;
    for (int ic = 0; ic < 192; ic++) {
        float v = __ldg(ip + (size_t)ic * HW);
        const float* wrow = ws + ic * 64;
#pragma unroll
        for (int o = 0; o < 64; o++) acc[o] = fmaf(v, wrow[o], acc[o]);
    }
    float* op = out + (size_t)b * 64 * HW + p;
#pragma unroll
    for (int o = 0; o < 64; o++) op[(size_t)o * HW] = acc[o];
}

// ---------------- mid convs: 64 -> 64 per branch, relu, write into m192 ----------------
// Block: 128 threads, 32x16 pixel tile, 8 output channels, 4 pixels/thread.
template<int R>
__global__ void k_conv64(const float* __restrict__ w, int brBase) {
    constexpr int K = 2 * R + 1, K2 = K * K;
    constexpr int TW = 32 + 2 * R, TH = 16 + 2 * R;
    __shared__ float tile[TH * TW];
    __shared__ float ws[8 * K2];
    int bx = blockIdx.x;
    int tx0 = (bx & 7) * 32, ty0 = (bx >> 3) * 16;
    int b = blockIdx.y >> 3, ocg = blockIdx.y & 7;
    int oc0 = ocg * 8;
    int tid = threadIdx.x;            // 128
    int row = tid >> 3, xq = (tid & 7) * 4;
    float acc[32];
#pragma unroll
    for (int t = 0; t < 32; t++) acc[t] = 0.f;
    const float* in = g_h64 + (size_t)b * 64 * HW;
    for (int ic = 0; ic < 64; ic++) {
        __syncthreads();
        for (int t = tid; t < TH * TW; t += 128) {
            int yy = ty0 - R + t / TW, xx = tx0 - R + t % TW;
            tile[t] = (yy >= 0 && yy < 256 && xx >= 0 && xx < 256)
                    ? in[(size_t)ic * HW + yy * 256 + xx] : 0.f;
        }
        for (int t = tid; t < 8 * K2; t += 128) {
            int o = t / K2;
            ws[t] = w[((size_t)(oc0 + o) * 64 + ic) * K2 + (t - o * K2)];
        }
        __syncthreads();
#pragma unroll
        for (int ky = 0; ky < K; ky++) {
#pragma unroll
            for (int kx = 0; kx < K; kx++) {
                int base = (row + ky) * TW + xq + kx;
                float t0 = tile[base], t1 = tile[base + 1];
                float t2 = tile[base + 2], t3 = tile[base + 3];
#pragma unroll
                for (int o = 0; o < 8; o++) {
                    float wv = ws[o * K2 + ky * K + kx];
                    acc[o * 4 + 0] = fmaf(t0, wv, acc[o * 4 + 0]);
                    acc[o * 4 + 1] = fmaf(t1, wv, acc[o * 4 + 1]);
                    acc[o * 4 + 2] = fmaf(t2, wv, acc[o * 4 + 2]);
                    acc[o * 4 + 3] = fmaf(t3, wv, acc[o * 4 + 3]);
                }
            }
        }
    }
    size_t ob = (size_t)(b * 192 + brBase + oc0) * HW + (ty0 + row) * 256 + tx0 + xq;
#pragma unroll
    for (int o = 0; o < 8; o++)
#pragma unroll
        for (int q = 0; q < 4; q++)
            g_m192[ob + (size_t)o * HW + q] = fmaxf(acc[o * 4 + q], 0.f);
}

// ---------------- BN stats: one block per channel (deterministic, no atomics) ----------------
__global__ void k_bnsum() {
    int c = blockIdx.x, tid = threadIdx.x;   // 256 threads
    double s = 0.0, s2 = 0.0;
    for (int t = tid; t < Bn * HW; t += 256) {
        int b = t >> 16, p = t & (HW - 1);
        float v = g_m64[(size_t)(b * 64 + c) * HW + p];
        s += v; s2 += (double)v * v;
    }
    __shared__ double sh1[256], sh2[256];
    sh1[tid] = s; sh2[tid] = s2; __syncthreads();
    for (int st = 128; st > 0; st >>= 1) {
        if (tid < st) { sh1[tid] += sh1[tid + st]; sh2[tid] += sh2[tid + st]; }
        __syncthreads();
    }
    if (tid == 0) { g_s1[c] = sh1[0]; g_s2[c] = sh2[0]; }
}

__global__ void k_bncoef(const float* __restrict__ bn_g, const float* __restrict__ bn_b) {
    int c = threadIdx.x;   // 64 threads
    double N = (double)(Bn * HW);
    double mean = g_s1[c] / N;
    double var = g_s2[c] / N - mean * mean;
    float a = (float)((double)bn_g[c] / sqrt(var + 1e-5));
    g_a[c] = a;
    g_bc[c] = bn_b[c] - (float)mean * a;
}

// ---------------- per (b,c) spatial mean of relu(bn(m)) ----------------
__global__ void k_ymean() {
    int c = blockIdx.x, b = blockIdx.y, tid = threadIdx.x;  // 256 threads
    float a = g_a[c], bc = g_bc[c];
    const float* mp = g_m64 + (size_t)(b * 64 + c) * HW;
    double s = 0.0;
    for (int p = tid; p < HW; p += 256)
        s += (double)fmaxf(fmaf(a, mp[p], bc), 0.f);
    __shared__ double sh[256];
    sh[tid] = s; __syncthreads();
    for (int st = 128; st > 0; st >>= 1) {
        if (tid < st) sh[tid] += sh[tid + st];
        __syncthreads();
    }
    if (tid == 0) g_ym[b * 64 + c] = sh[0] / (double)HW;
}

// ---------------- SE MLP: 64 -> 4 -> 64, sigmoid ----------------
__global__ void k_se(const float* __restrict__ se1, const float* __restrict__ se2) {
    __shared__ float t1[2][4];
    int tid = threadIdx.x;   // 64
    for (int b = 0; b < 2; b++) {
        if (tid < 4) {
            float s = 0.f;
            for (int c = 0; c < 64; c++) s += se1[tid * 64 + c] * (float)g_ym[b * 64 + c];
            t1[b][tid] = fmaxf(s, 0.f);
        }
    }
    __syncthreads();
    for (int b = 0; b < 2; b++) {
        float z = 0.f;
        for (int j = 0; j < 4; j++) z += se2[tid * 4 + j] * t1[b][j];
        g_y[b * 64 + tid] = 1.f / (1.f + expf(-z));
    }
}

// ---------------- final: noise = conv3x3(relu(bn(m))*y, wf); out = xp - noise ----------------
__global__ void k_final(const float* __restrict__ wf, float* __restrict__ out) {
    __shared__ float wy[576], sa[64], sb[64];
    int b = blockIdx.y;
    int tid = threadIdx.x;   // 256
    for (int t = tid; t < 576; t += 256) {
        int c = t / 9;
        wy[t] = __ldg(&wf[t]) * g_y[b * 64 + c];
    }
    if (tid < 64) { sa[tid] = g_a[tid]; sb[tid] = g_bc[tid]; }
    __syncthreads();
    int bx = blockIdx.x;
    int tx0 = (bx & 15) * 16, ty0 = (bx >> 4) * 16;
    int i = ty0 + (tid >> 4), j = tx0 + (tid & 15);
    float acc = 0.f;
    const float* mb = g_m64 + (size_t)b * 64 * HW;
    for (int c = 0; c < 64; c++) {
        float a = sa[c], bc = sb[c];
        const float* mc = mb + (size_t)c * HW;
#pragma unroll
        for (int ky = 0; ky < 3; ky++) {
            int yy = i + ky - 1; if (yy < 0 || yy > 255) continue;
#pragma unroll
            for (int kx = 0; kx < 3; kx++) {
                int xx = j + kx - 1; if (xx < 0 || xx > 255) continue;
                float v = __ldg(&mc[yy * 256 + xx]);
                float t = fmaxf(fmaf(a, v, bc), 0.f);
                acc = fmaf(wy[c * 9 + ky * 3 + kx], t, acc);
            }
        }
    }
    int p = i * 256 + j;
    out[b * HW + p] = g_xp[b * HW + p] - acc;
}

// ---------------- launch ----------------
extern "C" void kernel_launch(void* const* d_in, const int* in_sizes, int n_in,
                              void* d_out, int out_size) {
    const float* x    = (const float*)d_in[0];
    const float* w_i3 = (const float*)d_in[1];
    const float* w_i5 = (const float*)d_in[2];
    const float* w_i7 = (const float*)d_in[3];
    const float* w_p1 = (const float*)d_in[4];
    const float* wb3  = (const float*)d_in[5];
    const float* wb5  = (const float*)d_in[6];
    const float* wb7  = (const float*)d_in[7];
    const float* wbp  = (const float*)d_in[8];
    const float* bn_g = (const float*)d_in[9];
    const float* bn_b = (const float*)d_in[10];
    const float* se1  = (const float*)d_in[11];
    const float* se2  = (const float*)d_in[12];
    const float* wf   = (const float*)d_in[13];
    float* out = (float*)d_out;

    float *h192, *h64, *m192, *m64;
    cudaGetSymbolAddress((void**)&h192, g_h192);
    cudaGetSymbolAddress((void**)&h64,  g_h64);
    cudaGetSymbolAddress((void**)&m192, g_m192);
    cudaGetSymbolAddress((void**)&m64,  g_m64);

    k_pre<<<512, 256>>>(x);

    dim3 g1(256, 128);
    k_conv1<1><<<g1, 256>>>(w_i3, 0);
    k_conv1<2><<<g1, 256>>>(w_i5, 64);
    k_conv1<3><<<g1, 256>>>(w_i7, 128);

    k_1x1<<<dim3(256, 2), 256>>>(h192, w_p1, h64);

    dim3 g3(128, 16);
    k_conv64<1><<<g3, 128>>>(wb3, 0);
    k_conv64<2><<<g3, 128>>>(wb5, 64);
    k_conv64<3><<<g3, 128>>>(wb7, 128);

    k_1x1<<<dim3(256, 2), 256>>>(m192, wbp, m64);

    k_bnsum<<<64, 256>>>();
    k_bncoef<<<1, 64>>>(bn_g, bn_b);
    k_ymean<<<dim3(64, 2), 256>>>();
    k_se<<<1, 64>>>(se1, se2);
    k_final<<<dim3(256, 2), 256>>>(wf, out);
}

// round 2
// speedup vs baseline: 1.0716x; 1.0716x over previous
#include <cuda_runtime.h>
#include <math.h>

#define HW 65536
#define Bn 2

typedef unsigned long long ull;

// ---------------- packed f32x2 helpers ----------------
__device__ __forceinline__ void fma2(ull& acc, ull a, ull b) {
    asm("fma.rn.f32x2 %0, %1, %2, %0;" : "+l"(acc) : "l"(a), "l"(b));
}
__device__ __forceinline__ ull pack2(float lo, float hi) {
    ull r; asm("mov.b64 %0, {%1, %2};" : "=l"(r) : "f"(lo), "f"(hi)); return r;
}
__device__ __forceinline__ void unpack2(ull v, float& lo, float& hi) {
    asm("mov.b64 {%0, %1}, %2;" : "=f"(lo), "=f"(hi) : "l"(v));
}

// ---------------- scratch (static device memory, no allocations) ----------------
__device__ float g_xp[Bn * HW];            // preprocessed input
__device__ float g_h192[Bn * 192 * HW];    // first multi-scale conv output (relu)
__device__ float g_h64[Bn * 64 * HW];      // after 1x1 w_p1
__device__ float g_m192[Bn * 192 * HW];    // mid multi-scale conv output (relu)
__device__ float g_m64[Bn * 64 * HW];      // after 1x1 wbp (pre-BN)
__device__ double g_s1[64], g_s2[64];      // BN sums
__device__ float g_a[64], g_bc[64];        // BN scale/shift
__device__ double g_ym[Bn * 64];           // per (b,c) mean of relu(bn(m))
__device__ float g_y[Bn * 64];             // SE gate

// ---------------- preprocess: gamma blend + bilateral (reflect pad) ----------------
__device__ __forceinline__ float blendf(float v) {
    float g = fminf(fmaxf((v + 1.0f) * 0.5f, 1e-6f), 1.0f);
    return 0.6f * g + 0.4f * g * sqrtf(g);   // (1-a)*g + a*g^1.5
}

__global__ void k_pre(const float* __restrict__ x) {
    int idx = blockIdx.x * blockDim.x + threadIdx.x;
    if (idx >= Bn * HW) return;
    int b = idx >> 16, p = idx & (HW - 1);
    int i = p >> 8, j = p & 255;
    const float* xb = x + b * HW;
    float c = blendf(xb[p]);
    const int   di[13] = {-2,-1,-1,-1, 0, 0, 0, 0, 0, 1, 1, 1, 2};
    const int   dj[13] = { 0,-1, 0, 1,-2,-1, 0, 1, 2,-1, 0, 1, 0};
    const float sw[13] = {0.99920032f,0.99960008f,0.99980002f,0.99960008f,
                          0.99920032f,0.99980002f,1.0f,0.99980002f,0.99920032f,
                          0.99960008f,0.99980002f,0.99960008f,0.99920032f};
    float num = 0.f, den = 0.f;
#pragma unroll
    for (int t = 0; t < 13; t++) {
        int ri = i + di[t]; ri = ri < 0 ? -ri : (ri > 255 ? 510 - ri : ri);
        int rj = j + dj[t]; rj = rj < 0 ? -rj : (rj > 255 ? 510 - rj : rj);
        float sh = blendf(xb[ri * 256 + rj]);
        float d = sh - c;
        float w = sw[t] * expf(-200.0f * d * d);   // sigma_color = 0.05
        num = fmaf(w, sh, num);
        den += w;
    }
    g_xp[idx] = num / den;
}

// ---------------- generic KxK conv, IC -> 8 oc per block, packed f32x2 ----------------
// Block: 128 threads, 32x16 pixel tile, 8 output channels, 4 pixels/thread.
// Grid: (128 tiles, b*8 + ocg). Output written into a 192-channel tensor at brBase.
template<int R, int IC>
__global__ void k_conv(const float* __restrict__ in, const float* __restrict__ w,
                       float* __restrict__ out, int brBase) {
    constexpr int K = 2 * R + 1, K2 = K * K;
    constexpr int TW = 32 + 2 * R, TH = 16 + 2 * R;
    __shared__ __align__(16) float tile[TH * TW];
    __shared__ __align__(16) float wdup[8 * K2 * 2];   // weight duplicated into both lanes
    int bx = blockIdx.x;
    int tx0 = (bx & 7) * 32, ty0 = (bx >> 3) * 16;
    int b = blockIdx.y >> 3, ocg = blockIdx.y & 7;
    int oc0 = ocg * 8;
    int tid = threadIdx.x;            // 128
    int row = tid >> 3, xq = (tid & 7) * 4;
    ull acc[16];
#pragma unroll
    for (int t = 0; t < 16; t++) acc[t] = 0ull;
    const float* inb = in + (size_t)b * IC * HW;
    for (int ic = 0; ic < IC; ic++) {
        __syncthreads();
        const float* icp = inb + (size_t)ic * HW;
        for (int t = tid; t < TH * TW; t += 128) {
            int yy = ty0 - R + t / TW, xx = tx0 - R + t % TW;
            tile[t] = (yy >= 0 && yy < 256 && xx >= 0 && xx < 256)
                    ? __ldg(&icp[yy * 256 + xx]) : 0.f;
        }
        for (int t = tid; t < 8 * K2; t += 128) {
            int o = t / K2, tap = t - o * K2;
            float v = w[((size_t)(oc0 + o) * IC + ic) * K2 + tap];
            wdup[2 * t] = v; wdup[2 * t + 1] = v;
        }
        __syncthreads();
#pragma unroll
        for (int ky = 0; ky < K; ky++) {
#pragma unroll
            for (int kx = 0; kx < K; kx++) {
                int base = (row + ky) * TW + xq + kx;
                ull d01, d23;
                if ((kx & 1) == 0) {
                    d01 = *(const ull*)&tile[base];
                    d23 = *(const ull*)&tile[base + 2];
                } else {
                    d01 = pack2(tile[base], tile[base + 1]);
                    d23 = pack2(tile[base + 2], tile[base + 3]);
                }
#pragma unroll
                for (int o = 0; o < 8; o++) {
                    ull w2 = *(const ull*)&wdup[2 * (o * K2 + ky * K + kx)];
                    fma2(acc[2 * o], d01, w2);
                    fma2(acc[2 * o + 1], d23, w2);
                }
            }
        }
    }
    size_t ob = (size_t)(b * 192 + brBase + oc0) * HW + (ty0 + row) * 256 + tx0 + xq;
#pragma unroll
    for (int o = 0; o < 8; o++) {
        float f0, f1, f2, f3;
        unpack2(acc[2 * o], f0, f1);
        unpack2(acc[2 * o + 1], f2, f3);
        float* op = out + ob + (size_t)o * HW;
        op[0] = fmaxf(f0, 0.f); op[1] = fmaxf(f1, 0.f);
        op[2] = fmaxf(f2, 0.f); op[3] = fmaxf(f3, 0.f);
    }
}

// ---------------- 1x1 conv: 192 -> 64, two output channels packed per lane ----------------
__global__ void k_1x1(const float* __restrict__ in, const float* __restrict__ w,
                      float* __restrict__ out) {
    __shared__ __align__(16) float ws[192 * 64];   // ws[ic*64+oc] = w[oc*192+ic]  (48KB)
    int tid = threadIdx.x;
    for (int t = tid; t < 192 * 64; t += 256) {
        int oc = t & 63, ic = t >> 6;
        ws[t] = w[oc * 192 + ic];
    }
    __syncthreads();
    int b = blockIdx.y;
    int p = blockIdx.x * 256 + tid;
    const float* ip = in + (size_t)b * 192 * HW + p;
    ull acc[32];
#pragma unroll
    for (int t = 0; t < 32; t++) acc[t] = 0ull;
    for (int ic = 0; ic < 192; ic++) {
        float v = __ldg(ip + (size_t)ic * HW);
        ull v2 = pack2(v, v);
        const float* wr = ws + ic * 64;
#pragma unroll
        for (int o2 = 0; o2 < 32; o2++) {
            ull w2 = *(const ull*)&wr[2 * o2];   // adjacent oc pair, aligned LDS.64
            fma2(acc[o2], v2, w2);
        }
    }
    float* op = out + (size_t)b * 64 * HW + p;
#pragma unroll
    for (int o2 = 0; o2 < 32; o2++) {
        float lo, hi;
        unpack2(acc[o2], lo, hi);
        op[(size_t)(2 * o2) * HW] = lo;
        op[(size_t)(2 * o2 + 1) * HW] = hi;
    }
}

// ---------------- BN stats: one block per channel (deterministic, no atomics) ----------------
__global__ void k_bnsum() {
    int c = blockIdx.x, tid = threadIdx.x;   // 256 threads
    double s = 0.0, s2 = 0.0;
    for (int t = tid; t < Bn * HW; t += 256) {
        int b = t >> 16, p = t & (HW - 1);
        float v = g_m64[(size_t)(b * 64 + c) * HW + p];
        s += v; s2 += (double)v * v;
    }
    __shared__ double sh1[256], sh2[256];
    sh1[tid] = s; sh2[tid] = s2; __syncthreads();
    for (int st = 128; st > 0; st >>= 1) {
        if (tid < st) { sh1[tid] += sh1[tid + st]; sh2[tid] += sh2[tid + st]; }
        __syncthreads();
    }
    if (tid == 0) { g_s1[c] = sh1[0]; g_s2[c] = sh2[0]; }
}

__global__ void k_bncoef(const float* __restrict__ bn_g, const float* __restrict__ bn_b) {
    int c = threadIdx.x;   // 64 threads
    double N = (double)(Bn * HW);
    double mean = g_s1[c] / N;
    double var = g_s2[c] / N - mean * mean;
    float a = (float)((double)bn_g[c] / sqrt(var + 1e-5));
    g_a[c] = a;
    g_bc[c] = bn_b[c] - (float)mean * a;
}

// ---------------- per (b,c) spatial mean of relu(bn(m)) ----------------
__global__ void k_ymean() {
    int c = blockIdx.x, b = blockIdx.y, tid = threadIdx.x;  // 256 threads
    float a = g_a[c], bc = g_bc[c];
    const float* mp = g_m64 + (size_t)(b * 64 + c) * HW;
    double s = 0.0;
    for (int p = tid; p < HW; p += 256)
        s += (double)fmaxf(fmaf(a, mp[p], bc), 0.f);
    __shared__ double sh[256];
    sh[tid] = s; __syncthreads();
    for (int st = 128; st > 0; st >>= 1) {
        if (tid < st) sh[tid] += sh[tid + st];
        __syncthreads();
    }
    if (tid == 0) g_ym[b * 64 + c] = sh[0] / (double)HW;
}

// ---------------- SE MLP: 64 -> 4 -> 64, sigmoid ----------------
__global__ void k_se(const float* __restrict__ se1, const float* __restrict__ se2) {
    __shared__ float t1[2][4];
    int tid = threadIdx.x;   // 64
    for (int b = 0; b < 2; b++) {
        if (tid < 4) {
            float s = 0.f;
            for (int c = 0; c < 64; c++) s += se1[tid * 64 + c] * (float)g_ym[b * 64 + c];
            t1[b][tid] = fmaxf(s, 0.f);
        }
    }
    __syncthreads();
    for (int b = 0; b < 2; b++) {
        float z = 0.f;
        for (int j = 0; j < 4; j++) z += se2[tid * 4 + j] * t1[b][j];
        g_y[b * 64 + tid] = 1.f / (1.f + expf(-z));
    }
}

// ---------------- final: noise = conv3x3(relu(bn(m))*y, wf); out = xp - noise ----------------
__global__ void k_final(const float* __restrict__ wf, float* __restrict__ out) {
    __shared__ float wy[576], sa[64], sb[64];
    int b = blockIdx.y;
    int tid = threadIdx.x;   // 256
    for (int t = tid; t < 576; t += 256) {
        int c = t / 9;
        wy[t] = __ldg(&wf[t]) * g_y[b * 64 + c];
    }
    if (tid < 64) { sa[tid] = g_a[tid]; sb[tid] = g_bc[tid]; }
    __syncthreads();
    int bx = blockIdx.x;
    int tx0 = (bx & 15) * 16, ty0 = (bx >> 4) * 16;
    int i = ty0 + (tid >> 4), j = tx0 + (tid & 15);
    float acc = 0.f;
    const float* mb = g_m64 + (size_t)b * 64 * HW;
    for (int c = 0; c < 64; c++) {
        float a = sa[c], bc = sb[c];
        const float* mc = mb + (size_t)c * HW;
#pragma unroll
        for (int ky = 0; ky < 3; ky++) {
            int yy = i + ky - 1; if (yy < 0 || yy > 255) continue;
#pragma unroll
            for (int kx = 0; kx < 3; kx++) {
                int xx = j + kx - 1; if (xx < 0 || xx > 255) continue;
                float v = __ldg(&mc[yy * 256 + xx]);
                float t = fmaxf(fmaf(a, v, bc), 0.f);
                acc = fmaf(wy[c * 9 + ky * 3 + kx], t, acc);
            }
        }
    }
    int p = i * 256 + j;
    out[b * HW + p] = g_xp[b * HW + p] - acc;
}

// ---------------- launch ----------------
extern "C" void kernel_launch(void* const* d_in, const int* in_sizes, int n_in,
                              void* d_out, int out_size) {
    const float* x    = (const float*)d_in[0];
    const float* w_i3 = (const float*)d_in[1];
    const float* w_i5 = (const float*)d_in[2];
    const float* w_i7 = (const float*)d_in[3];
    const float* w_p1 = (const float*)d_in[4];
    const float* wb3  = (const float*)d_in[5];
    const float* wb5  = (const float*)d_in[6];
    const float* wb7  = (const float*)d_in[7];
    const float* wbp  = (const float*)d_in[8];
    const float* bn_g = (const float*)d_in[9];
    const float* bn_b = (const float*)d_in[10];
    const float* se1  = (const float*)d_in[11];
    const float* se2  = (const float*)d_in[12];
    const float* wf   = (const float*)d_in[13];
    float* out = (float*)d_out;

    float *xp, *h192, *h64, *m192, *m64;
    cudaGetSymbolAddress((void**)&xp,   g_xp);
    cudaGetSymbolAddress((void**)&h192, g_h192);
    cudaGetSymbolAddress((void**)&h64,  g_h64);
    cudaGetSymbolAddress((void**)&m192, g_m192);
    cudaGetSymbolAddress((void**)&m64,  g_m64);

    k_pre<<<512, 256>>>(x);

    dim3 gc(128, 16);   // 128 tiles of 32x16, (b,ocg)
    k_conv<1, 1><<<gc, 128>>>(xp, w_i3, h192, 0);
    k_conv<2, 1><<<gc, 128>>>(xp, w_i5, h192, 64);
    k_conv<3, 1><<<gc, 128>>>(xp, w_i7, h192, 128);

    k_1x1<<<dim3(256, 2), 256>>>(h192, w_p1, h64);

    k_conv<1, 64><<<gc, 128>>>(h64, wb3, m192, 0);
    k_conv<2, 64><<<gc, 128>>>(h64, wb5, m192, 64);
    k_conv<3, 64><<<gc, 128>>>(h64, wb7, m192, 128);

    k_1x1<<<dim3(256, 2), 256>>>(m192, wbp, m64);

    k_bnsum<<<64, 256>>>();
    k_bncoef<<<1, 64>>>(bn_g, bn_b);
    k_ymean<<<dim3(64, 2), 256>>>();
    k_se<<<1, 64>>>(se1, se2);
    k_final<<<dim3(256, 2), 256>>>(wf, out);
}

// round 4
// speedup vs baseline: 1.1087x; 1.0346x over previous
#include <cuda_runtime.h>
#include <math.h>

#define HW 65536
#define Bn 2

typedef unsigned long long ull;

// ---------------- packed f32x2 helpers ----------------
__device__ __forceinline__ void fma2(ull& acc, ull a, ull b) {
    asm("fma.rn.f32x2 %0, %1, %2, %0;" : "+l"(acc) : "l"(a), "l"(b));
}
__device__ __forceinline__ ull pack2(float lo, float hi) {
    ull r; asm("mov.b64 %0, {%1, %2};" : "=l"(r) : "f"(lo), "f"(hi)); return r;
}
__device__ __forceinline__ void unpack2(ull v, float& lo, float& hi) {
    asm("mov.b64 {%0, %1}, %2;" : "=f"(lo), "=f"(hi) : "l"(v));
}

// ---------------- scratch ----------------
__device__ float g_xp[Bn * HW];
__device__ float g_h192[Bn * 192 * HW];
__device__ float g_h64[Bn * 64 * HW];
__device__ float g_m192[Bn * 192 * HW];
__device__ float g_m64[Bn * 64 * HW];
__device__ double g_ps1[64][4], g_ps2[64][4];
__device__ float g_a[64], g_bc[64];
__device__ double g_ym[Bn * 64];
__device__ float g_y[Bn * 64];

// ---------------- preprocess ----------------
__device__ __forceinline__ float blendf(float v) {
    float g = fminf(fmaxf((v + 1.0f) * 0.5f, 1e-6f), 1.0f);
    return 0.6f * g + 0.4f * g * sqrtf(g);
}

__global__ void k_pre(const float* __restrict__ x) {
    int idx = blockIdx.x * blockDim.x + threadIdx.x;
    if (idx >= Bn * HW) return;
    int b = idx >> 16, p = idx & (HW - 1);
    int i = p >> 8, j = p & 255;
    const float* xb = x + b * HW;
    float c = blendf(xb[p]);
    const int   di[13] = {-2,-1,-1,-1, 0, 0, 0, 0, 0, 1, 1, 1, 2};
    const int   dj[13] = { 0,-1, 0, 1,-2,-1, 0, 1, 2,-1, 0, 1, 0};
    const float sw[13] = {0.99920032f,0.99960008f,0.99980002f,0.99960008f,
                          0.99920032f,0.99980002f,1.0f,0.99980002f,0.99920032f,
                          0.99960008f,0.99980002f,0.99960008f,0.99920032f};
    float num = 0.f, den = 0.f;
#pragma unroll
    for (int t = 0; t < 13; t++) {
        int ri = i + di[t]; ri = ri < 0 ? -ri : (ri > 255 ? 510 - ri : ri);
        int rj = j + dj[t]; rj = rj < 0 ? -rj : (rj > 255 ? 510 - rj : rj);
        float sh = blendf(xb[ri * 256 + rj]);
        float d = sh - c;
        float w = sw[t] * expf(-200.0f * d * d);
        num = fmaf(w, sh, num);
        den += w;
    }
    g_xp[idx] = num / den;
}

// ---------------- KxK conv: IC -> 4 oc per block, 8px x 2oc per thread, f32x2 ----
// Block 256 threads, 32x32 output tile. Double-buffered smem, register prefetch.
// Grid: (64 tiles, Bn*16) ; blockIdx.y = b*16 + ocg, oc0 = ocg*4.
template<int R, int IC>
__global__ void __launch_bounds__(256) k_conv(
        const float* __restrict__ in, const float* __restrict__ w,
        float* __restrict__ out, int brBase) {
    constexpr int K = 2 * R + 1, K2 = K * K;
    constexpr int TW = 32 + 2 * R, TH = 32 + 2 * R;
    constexpr int ELE = TH * TW;
    constexpr int PER = (ELE + 255) / 256;
    constexpr int WN = 4 * K2;            // weights per ic (4 oc)
    constexpr int NP = 4 + R;             // even-pair count in row cache
    constexpr int NO = R + 3;             // odd-pair count
    __shared__ __align__(16) float tile[2][ELE];
    __shared__ __align__(16) float ws[2][WN * 2];

    int bx = blockIdx.x;
    int tx0 = (bx & 7) * 32, ty0 = (bx >> 3) * 32;
    int b = blockIdx.y >> 4, ocg = blockIdx.y & 15;
    int oc0 = ocg * 4;
    int tid = threadIdx.x;
    int ocp = tid >> 7;                    // 0..1 -> oc pair
    int r7  = tid & 127;
    int row = r7 >> 2;                     // 0..31
    int x0  = (r7 & 3) * 8;                // 0,8,16,24

    ull accA[4], accB[4];
#pragma unroll
    for (int j = 0; j < 4; j++) { accA[j] = 0ull; accB[j] = 0ull; }

    const float* inb = in + (size_t)b * IC * HW;

    // initial load of ic=0 into buffer 0
    {
        const float* icp = inb;
#pragma unroll
        for (int u = 0; u < PER; u++) {
            int t = tid + u * 256;
            if (t < ELE) {
                int yy = ty0 - R + t / TW, xx = tx0 - R + t % TW;
                tile[0][t] = (yy >= 0 && yy < 256 && xx >= 0 && xx < 256)
                           ? __ldg(&icp[yy * 256 + xx]) : 0.f;
            }
        }
        if (tid < WN) {
            int o = tid / K2, tap = tid - o * K2;
            float v = __ldg(&w[((size_t)(oc0 + o) * IC) * K2 + tap]);
            ws[0][2 * tid] = v; ws[0][2 * tid + 1] = v;
        }
    }
    __syncthreads();

    for (int ic = 0; ic < IC; ic++) {
        int cur = ic & 1, nxt = cur ^ 1;
        // prefetch next ic into registers
        float pv[PER]; float pw = 0.f;
        bool more = (ic + 1 < IC);
        if (more) {
            const float* icp = inb + (size_t)(ic + 1) * HW;
#pragma unroll
            for (int u = 0; u < PER; u++) {
                int t = tid + u * 256;
                pv[u] = 0.f;
                if (t < ELE) {
                    int yy = ty0 - R + t / TW, xx = tx0 - R + t % TW;
                    if (yy >= 0 && yy < 256 && xx >= 0 && xx < 256)
                        pv[u] = __ldg(&icp[yy * 256 + xx]);
                }
            }
            if (tid < WN) {
                int o = tid / K2, tap = tid - o * K2;
                pw = __ldg(&w[((size_t)(oc0 + o) * IC + (ic + 1)) * K2 + tap]);
            }
        }
        // compute on current buffer
        const float* tl = tile[cur];
        const float* wp = ws[cur];
#pragma unroll
        for (int ky = 0; ky < K; ky++) {
            int base = (row + ky) * TW + x0;
            ull rc[NP];
#pragma unroll
            for (int t = 0; t < NP; t++) rc[t] = *(const ull*)&tl[base + 2 * t];
            float fl[2 * NP];
#pragma unroll
            for (int t = 0; t < NP; t++) unpack2(rc[t], fl[2 * t], fl[2 * t + 1]);
            ull ro[NO];
#pragma unroll
            for (int t = 0; t < NO; t++) ro[t] = pack2(fl[2 * t + 1], fl[2 * t + 2]);
#pragma unroll
            for (int kx = 0; kx < K; kx++) {
                int tap = ky * K + kx;
                ull wa = *(const ull*)&wp[(2 * ocp * K2 + tap) * 2];
                ull wb = *(const ull*)&wp[((2 * ocp + 1) * K2 + tap) * 2];
#pragma unroll
                for (int j = 0; j < 4; j++) {
                    int s = kx + 2 * j;
                    ull d = (s & 1) ? ro[s >> 1] : rc[s >> 1];
                    fma2(accA[j], d, wa);
                    fma2(accB[j], d, wb);
                }
            }
        }
        // store prefetched data into the other buffer
        if (more) {
#pragma unroll
            for (int u = 0; u < PER; u++) {
                int t = tid + u * 256;
                if (t < ELE) tile[nxt][t] = pv[u];
            }
            if (tid < WN) { ws[nxt][2 * tid] = pw; ws[nxt][2 * tid + 1] = pw; }
        }
        __syncthreads();
    }

    // write out: 2 oc x 8 px, relu
    size_t ob = (size_t)(b * 192 + brBase + oc0 + 2 * ocp) * HW
              + (ty0 + row) * 256 + tx0 + x0;
    float* opA = out + ob;
    float* opB = out + ob + HW;
#pragma unroll
    for (int j = 0; j < 4; j++) {
        float a0, a1, b0, b1;
        unpack2(accA[j], a0, a1);
        unpack2(accB[j], b0, b1);
        opA[2 * j] = fmaxf(a0, 0.f); opA[2 * j + 1] = fmaxf(a1, 0.f);
        opB[2 * j] = fmaxf(b0, 0.f); opB[2 * j + 1] = fmaxf(b1, 0.f);
    }
}

// ---------------- 1x1 conv: 192 -> 64, 2 px/thread, 32 oc/block ----------------
// grid: (128, 4): blockIdx.y = b*2 + ocg ; ocbase = ocg*32
__global__ void __launch_bounds__(256) k_1x1(
        const float* __restrict__ in, const float* __restrict__ w,
        float* __restrict__ out) {
    __shared__ __align__(16) float wsd[192 * 32 * 2];   // 48KB dup'd
    int tid = threadIdx.x;
    int b = blockIdx.y >> 1, ocg = blockIdx.y & 1;
    int ocbase = ocg * 32;
    for (int t = tid; t < 192 * 32; t += 256) {
        int ic = t >> 5, o = t & 31;
        float v = w[(ocbase + o) * 192 + ic];
        wsd[2 * t] = v; wsd[2 * t + 1] = v;
    }
    __syncthreads();
    int p0 = blockIdx.x * 512 + tid * 2;
    const float* ip = in + (size_t)b * 192 * HW + p0;
    ull acc[32];
#pragma unroll
    for (int t = 0; t < 32; t++) acc[t] = 0ull;
    ull d = *(const ull*)ip;
    for (int ic = 0; ic < 192; ic++) {
        ull dn = 0ull;
        if (ic + 1 < 192) dn = *(const ull*)(ip + (size_t)(ic + 1) * HW);
        const float* wr = wsd + ic * 64;
#pragma unroll
        for (int o = 0; o < 32; o++) {
            ull w2 = *(const ull*)&wr[2 * o];
            fma2(acc[o], d, w2);
        }
        d = dn;
    }
    float* op = out + (size_t)b * 64 * HW + p0;
#pragma unroll
    for (int o = 0; o < 32; o++)
        *(ull*)&op[(size_t)(ocbase + o) * HW] = acc[o];
}

// ---------------- BN stats: 4 blocks per channel, 4 independent accumulators ----
__global__ void k_bnsum() {
    int c = blockIdx.x >> 2, seg = blockIdx.x & 3, tid = threadIdx.x;  // 256 thr
    int base = seg * 32768;   // over combined (b,p) index space of 131072
    double s[4] = {0, 0, 0, 0}, s2[4] = {0, 0, 0, 0};
    for (int u = 0; u < 32; u++) {
        int t = base + u * 1024 + tid * 4;
#pragma unroll
        for (int q = 0; q < 4; q++) {
            int tt = t + q;
            int bb = tt >> 16, p = tt & (HW - 1);
            float v = g_m64[(size_t)(bb * 64 + c) * HW + p];
            s[q] += v; s2[q] += (double)v * v;
        }
    }
    double ss = (s[0] + s[1]) + (s[2] + s[3]);
    double ss2 = (s2[0] + s2[1]) + (s2[2] + s2[3]);
    __shared__ double sh1[256], sh2[256];
    sh1[tid] = ss; sh2[tid] = ss2; __syncthreads();
    for (int st = 128; st > 0; st >>= 1) {
        if (tid < st) { sh1[tid] += sh1[tid + st]; sh2[tid] += sh2[tid + st]; }
        __syncthreads();
    }
    if (tid == 0) { g_ps1[c][seg] = sh1[0]; g_ps2[c][seg] = sh2[0]; }
}

__global__ void k_bncoef(const float* __restrict__ bn_g, const float* __restrict__ bn_b) {
    int c = threadIdx.x;
    double N = (double)(Bn * HW);
    double s1 = (g_ps1[c][0] + g_ps1[c][1]) + (g_ps1[c][2] + g_ps1[c][3]);
    double s2 = (g_ps2[c][0] + g_ps2[c][1]) + (g_ps2[c][2] + g_ps2[c][3]);
    double mean = s1 / N;
    double var = s2 / N - mean * mean;
    float a = (float)((double)bn_g[c] / sqrt(var + 1e-5));
    g_a[c] = a;
    g_bc[c] = bn_b[c] - (float)mean * a;
}

// ---------------- per (b,c) spatial mean of relu(bn(m)) ----------------
__global__ void k_ymean() {
    int c = blockIdx.x, b = blockIdx.y, tid = threadIdx.x;  // 256 threads
    float a = g_a[c], bc = g_bc[c];
    const float* mp = g_m64 + (size_t)(b * 64 + c) * HW;
    double s[4] = {0, 0, 0, 0};
    for (int p = tid * 4; p < HW; p += 1024) {
#pragma unroll
        for (int q = 0; q < 4; q++)
            s[q] += (double)fmaxf(fmaf(a, mp[p + q], bc), 0.f);
    }
    __shared__ double sh[256];
    sh[tid] = (s[0] + s[1]) + (s[2] + s[3]); __syncthreads();
    for (int st = 128; st > 0; st >>= 1) {
        if (tid < st) sh[tid] += sh[tid + st];
        __syncthreads();
    }
    if (tid == 0) g_ym[b * 64 + c] = sh[0] / (double)HW;
}

// ---------------- SE MLP ----------------
__global__ void k_se(const float* __restrict__ se1, const float* __restrict__ se2) {
    __shared__ float t1[2][4];
    int tid = threadIdx.x;   // 64
    for (int b = 0; b < 2; b++) {
        if (tid < 4) {
            float s = 0.f;
            for (int c = 0; c < 64; c++) s += se1[tid * 64 + c] * (float)g_ym[b * 64 + c];
            t1[b][tid] = fmaxf(s, 0.f);
        }
    }
    __syncthreads();
    for (int b = 0; b < 2; b++) {
        float z = 0.f;
        for (int j = 0; j < 4; j++) z += se2[tid * 4 + j] * t1[b][j];
        g_y[b * 64 + tid] = 1.f / (1.f + expf(-z));
    }
}

// ---------------- final ----------------
__global__ void k_final(const float* __restrict__ wf, float* __restrict__ out) {
    __shared__ float wy[576], sa[64], sb[64];
    int b = blockIdx.y;
    int tid = threadIdx.x;   // 256
    for (int t = tid; t < 576; t += 256) {
        int c = t / 9;
        wy[t] = __ldg(&wf[t]) * g_y[b * 64 + c];
    }
    if (tid < 64) { sa[tid] = g_a[tid]; sb[tid] = g_bc[tid]; }
    __syncthreads();
    int bx = blockIdx.x;
    int tx0 = (bx & 15) * 16, ty0 = (bx >> 4) * 16;
    int i = ty0 + (tid >> 4), j = tx0 + (tid & 15);
    float acc = 0.f;
    const float* mb = g_m64 + (size_t)b * 64 * HW;
    for (int c = 0; c < 64; c++) {
        float a = sa[c], bc = sb[c];
        const float* mc = mb + (size_t)c * HW;
#pragma unroll
        for (int ky = 0; ky < 3; ky++) {
            int yy = i + ky - 1; if (yy < 0 || yy > 255) continue;
#pragma unroll
            for (int kx = 0; kx < 3; kx++) {
                int xx = j + kx - 1; if (xx < 0 || xx > 255) continue;
                float v = __ldg(&mc[yy * 256 + xx]);
                float t = fmaxf(fmaf(a, v, bc), 0.f);
                acc = fmaf(wy[c * 9 + ky * 3 + kx], t, acc);
            }
        }
    }
    int p = i * 256 + j;
    out[b * HW + p] = g_xp[b * HW + p] - acc;
}

// ---------------- launch ----------------
extern "C" void kernel_launch(void* const* d_in, const int* in_sizes, int n_in,
                              void* d_out, int out_size) {
    const float* x    = (const float*)d_in[0];
    const float* w_i3 = (const float*)d_in[1];
    const float* w_i5 = (const float*)d_in[2];
    const float* w_i7 = (const float*)d_in[3];
    const float* w_p1 = (const float*)d_in[4];
    const float* wb3  = (const float*)d_in[5];
    const float* wb5  = (const float*)d_in[6];
    const float* wb7  = (const float*)d_in[7];
    const float* wbp  = (const float*)d_in[8];
    const float* bn_g = (const float*)d_in[9];
    const float* bn_b = (const float*)d_in[10];
    const float* se1  = (const float*)d_in[11];
    const float* se2  = (const float*)d_in[12];
    const float* wf   = (const float*)d_in[13];
    float* out = (float*)d_out;

    float *xp, *h192, *h64, *m192, *m64;
    cudaGetSymbolAddress((void**)&xp,   g_xp);
    cudaGetSymbolAddress((void**)&h192, g_h192);
    cudaGetSymbolAddress((void**)&h64,  g_h64);
    cudaGetSymbolAddress((void**)&m192, g_m192);
    cudaGetSymbolAddress((void**)&m64,  g_m64);

    k_pre<<<512, 256>>>(x);

    dim3 gc(64, Bn * 16);
    k_conv<1, 1><<<gc, 256>>>(xp, w_i3, h192, 0);
    k_conv<2, 1><<<gc, 256>>>(xp, w_i5, h192, 64);
    k_conv<3, 1><<<gc, 256>>>(xp, w_i7, h192, 128);

    k_1x1<<<dim3(128, 4), 256>>>(h192, w_p1, h64);

    k_conv<1, 64><<<gc, 256>>>(h64, wb3, m192, 0);
    k_conv<2, 64><<<gc, 256>>>(h64, wb5, m192, 64);
    k_conv<3, 64><<<gc, 256>>>(h64, wb7, m192, 128);

    k_1x1<<<dim3(128, 4), 256>>>(m192, wbp, m64);

    k_bnsum<<<256, 256>>>();
    k_bncoef<<<1, 64>>>(bn_g, bn_b);
    k_ymean<<<dim3(64, 2), 256>>>();
    k_se<<<1, 64>>>(se1, se2);
    k_final<<<dim3(256, 2), 256>>>(wf, out);
}

// round 5
// speedup vs baseline: 2.3120x; 2.0854x over previous
#include <cuda_runtime.h>
#include <cuda_bf16.h>
#include <math.h>

#define HW 65536
#define Bn 2

typedef unsigned long long ull;

// ---------------- scratch ----------------
__device__ float g_xp[Bn * HW];
__device__ float g_h192[Bn * 192 * HW];
__device__ float g_h64[Bn * 64 * HW];
__device__ float g_m192[Bn * 192 * HW];
__device__ float g_m64[Bn * 64 * HW];
__device__ double g_ps1[64][4], g_ps2[64][4];
__device__ float g_a[64], g_bc[64];
__device__ double g_ym[Bn * 64];
__device__ float g_y[Bn * 64];
// channel-last bf16 hi|lo input for mid convs: [b][y][x][128]
__device__ __nv_bfloat16 g_hc[(size_t)Bn * HW * 128];
// per-tap weights, rows [oc][hi 64 | lo 64] bf16 (permuted ic order)
__device__ __nv_bfloat16 g_wc3[9 * 64 * 128];
__device__ __nv_bfloat16 g_wc5[25 * 64 * 128];
__device__ __nv_bfloat16 g_wc7[49 * 64 * 128];

// permuted within-16 element index (k-pair interleave so LDS.64 = (klo,khi) frag regs)
__device__ __host__ __forceinline__ int permCol(int ic) {
    int jj = ic & 15, q = jj >> 1, e = jj & 1;
    int sp = (q < 4) ? 2 * q : 2 * (q - 4) + 1;
    return (ic & ~15) + 2 * sp + e;
}

// ---------------- preprocess ----------------
__device__ __forceinline__ float blendf(float v) {
    float g = fminf(fmaxf((v + 1.0f) * 0.5f, 1e-6f), 1.0f);
    return 0.6f * g + 0.4f * g * sqrtf(g);
}

__global__ void k_pre(const float* __restrict__ x) {
    int idx = blockIdx.x * blockDim.x + threadIdx.x;
    if (idx >= Bn * HW) return;
    int b = idx >> 16, p = idx & (HW - 1);
    int i = p >> 8, j = p & 255;
    const float* xb = x + b * HW;
    float c = blendf(xb[p]);
    const int   di[13] = {-2,-1,-1,-1, 0, 0, 0, 0, 0, 1, 1, 1, 2};
    const int   dj[13] = { 0,-1, 0, 1,-2,-1, 0, 1, 2,-1, 0, 1, 0};
    const float sw[13] = {0.99920032f,0.99960008f,0.99980002f,0.99960008f,
                          0.99920032f,0.99980002f,1.0f,0.99980002f,0.99920032f,
                          0.99960008f,0.99980002f,0.99960008f,0.99920032f};
    float num = 0.f, den = 0.f;
#pragma unroll
    for (int t = 0; t < 13; t++) {
        int ri = i + di[t]; ri = ri < 0 ? -ri : (ri > 255 ? 510 - ri : ri);
        int rj = j + dj[t]; rj = rj < 0 ? -rj : (rj > 255 ? 510 - rj : rj);
        float sh = blendf(xb[ri * 256 + rj]);
        float d = sh - c;
        float w = sw[t] * expf(-200.0f * d * d);
        num = fmaf(w, sh, num);
        den += w;
    }
    g_xp[idx] = num / den;
}

// ---------------- KxK conv for IC=1 (input convs), scalar fp32 ----------------
template<int R>
__global__ void k_conv1(const float* __restrict__ in, const float* __restrict__ w,
                        float* __restrict__ out, int brBase) {
    constexpr int K = 2 * R + 1, K2 = K * K;
    constexpr int TW = 32 + 2 * R, TH = 16 + 2 * R;
    __shared__ float tile[TH * TW];
    __shared__ float ws[8 * K2];
    int bx = blockIdx.x;
    int tx0 = (bx & 7) * 32, ty0 = (bx >> 3) * 16;
    int b = blockIdx.y >> 3, ocg = blockIdx.y & 7;
    int oc0 = ocg * 8;
    int tid = threadIdx.x;            // 128
    int row = tid >> 3, xq = (tid & 7) * 4;
    const float* icp = in + (size_t)b * HW;
    for (int t = tid; t < TH * TW; t += 128) {
        int yy = ty0 - R + t / TW, xx = tx0 - R + t % TW;
        tile[t] = (yy >= 0 && yy < 256 && xx >= 0 && xx < 256)
                ? __ldg(&icp[yy * 256 + xx]) : 0.f;
    }
    for (int t = tid; t < 8 * K2; t += 128) {
        int o = t / K2;
        ws[t] = w[(size_t)(oc0 + o) * K2 + (t - o * K2)];
    }
    __syncthreads();
    float acc[8][4];
#pragma unroll
    for (int o = 0; o < 8; o++)
#pragma unroll
        for (int q = 0; q < 4; q++) acc[o][q] = 0.f;
#pragma unroll
    for (int ky = 0; ky < K; ky++) {
#pragma unroll
        for (int kx = 0; kx < K; kx++) {
            int base = (row + ky) * TW + xq + kx;
            float t0 = tile[base], t1 = tile[base + 1];
            float t2 = tile[base + 2], t3 = tile[base + 3];
#pragma unroll
            for (int o = 0; o < 8; o++) {
                float wv = ws[o * K2 + ky * K + kx];
                acc[o][0] = fmaf(t0, wv, acc[o][0]);
                acc[o][1] = fmaf(t1, wv, acc[o][1]);
                acc[o][2] = fmaf(t2, wv, acc[o][2]);
                acc[o][3] = fmaf(t3, wv, acc[o][3]);
            }
        }
    }
    size_t ob = (size_t)(b * 192 + brBase + oc0) * HW + (ty0 + row) * 256 + tx0 + xq;
#pragma unroll
    for (int o = 0; o < 8; o++)
#pragma unroll
        for (int q = 0; q < 4; q++)
            out[ob + (size_t)o * HW + q] = fmaxf(acc[o][q], 0.f);
}

// ---------------- 1x1 conv: 192 -> 64, 2 px/thread, 32 oc/block ----------------
__global__ void __launch_bounds__(256) k_1x1(
        const float* __restrict__ in, const float* __restrict__ w,
        float* __restrict__ out) {
    __shared__ __align__(16) float wsd[192 * 64];
    int tid = threadIdx.x;
    int b = blockIdx.y >> 1, ocg = blockIdx.y & 1;
    int ocbase = ocg * 32;
    for (int t = tid; t < 192 * 32; t += 256) {
        int ic = t >> 5, o = t & 31;
        float v = w[(ocbase + o) * 192 + ic];
        wsd[2 * t] = v; wsd[2 * t + 1] = v;
    }
    __syncthreads();
    int p0 = blockIdx.x * 512 + tid * 2;
    const float* ip = in + (size_t)b * 192 * HW + p0;
    float acc[32][2];
#pragma unroll
    for (int t = 0; t < 32; t++) { acc[t][0] = 0.f; acc[t][1] = 0.f; }
    float2 d = *(const float2*)ip;
    for (int ic = 0; ic < 192; ic++) {
        float2 dn = make_float2(0.f, 0.f);
        if (ic + 1 < 192) dn = *(const float2*)(ip + (size_t)(ic + 1) * HW);
        const float* wr = wsd + ic * 64;
#pragma unroll
        for (int o = 0; o < 32; o++) {
            float wv = wr[2 * o];
            acc[o][0] = fmaf(d.x, wv, acc[o][0]);
            acc[o][1] = fmaf(d.y, wv, acc[o][1]);
        }
        d = dn;
    }
    float* op = out + (size_t)b * 64 * HW + p0;
#pragma unroll
    for (int o = 0; o < 32; o++)
        *(float2*)&op[(size_t)(ocbase + o) * HW] = make_float2(acc[o][0], acc[o][1]);
}

// ---------------- transpose/convert h64 -> channel-last bf16 hi|lo ----------------
__global__ void __launch_bounds__(256) k_tr(const float* __restrict__ h64) {
    __shared__ __nv_bfloat16 sm[64 * 136];   // row stride 136 elems (272B)
    int tid = threadIdx.x;
    int b = blockIdx.y;
    int pxb = blockIdx.x * 64;
    // phase 1: coalesced planar reads, split hi/lo, scatter into smem
    for (int i = 0; i < 16; i++) {
        int ic = i * 4 + (tid >> 6);
        int px = tid & 63;
        float v = h64[((size_t)(b * 64 + ic)) * HW + pxb + px];
        __nv_bfloat16 hi = __float2bfloat16_rn(v);
        float lo = v - __bfloat162float(hi);
        int col = permCol(ic);
        sm[px * 136 + col] = hi;
        sm[px * 136 + 64 + col] = __float2bfloat16_rn(lo);
    }
    __syncthreads();
    // phase 2: coalesced channel-last writes (each thread one 64B chunk of a px row)
    int px = tid >> 2, ch = (tid & 3) * 32;
    __nv_bfloat16* dst = g_hc + ((size_t)b * HW + pxb + px) * 128 + ch;
    const uint4* src = (const uint4*)(sm + px * 136 + ch);
#pragma unroll
    for (int i = 0; i < 4; i++)
        *(uint4*)(dst + i * 8) = src[i];
}

// ---------------- weight convert: [oc][ic][K2] fp32 -> per-tap bf16 hi|lo rows ----
__global__ void k_wc(const float* __restrict__ w, __nv_bfloat16* __restrict__ wc) {
    int tap = blockIdx.y;
    int K2 = gridDim.y;
    int t = blockIdx.x * 256 + threadIdx.x;   // 0..4095
    int oc = t >> 6, ic = t & 63;
    float v = w[((size_t)oc * 64 + ic) * K2 + tap];
    __nv_bfloat16 hi = __float2bfloat16_rn(v);
    float lo = v - __bfloat162float(hi);
    __nv_bfloat16* row = wc + ((size_t)tap * 64 + oc) * 128;
    int col = permCol(ic);
    row[col] = hi;
    row[64 + col] = __float2bfloat16_rn(lo);
}

// ---------------- bf16 mma helper ----------------
__device__ __forceinline__ void mma_bf16(float* d, unsigned a0, unsigned a1,
                                         unsigned a2, unsigned a3,
                                         unsigned b0, unsigned b1) {
    asm("mma.sync.aligned.m16n8k16.row.col.f32.bf16.bf16.f32 "
        "{%0,%1,%2,%3},{%4,%5,%6,%7},{%8,%9},{%0,%1,%2,%3};"
        : "+f"(d[0]), "+f"(d[1]), "+f"(d[2]), "+f"(d[3])
        : "r"(a0), "r"(a1), "r"(a2), "r"(a3), "r"(b0), "r"(b1));
}

// ---------------- mid conv: 64->64, KxK, tensor-core bf16 hi/lo ----------------
// CTA 256 thr: tile 32x(x) * 8(y) px, all 64 oc. Warps: 4(M:2y) x 2(N:32oc).
template<int R>
__global__ void __launch_bounds__(256) k_mconv(
        const __nv_bfloat16* __restrict__ wc,
        float* __restrict__ out, int brBase) {
    constexpr int K = 2 * R + 1, K2 = K * K;
    constexpr int TWX = 32 + 2 * R, TWY = 8 + 2 * R, ROWS = TWX * TWY;
    constexpr int RB = 272;                 // padded row bytes (128 bf16 + 16B)
    constexpr int WB1 = 64 * 272;           // one weight buffer
    extern __shared__ char smem[];
    char* tile = smem;                      // ROWS * 272
    char* wbuf = smem + ROWS * RB;          // 2 * WB1

    int tid = threadIdx.x;
    int b = blockIdx.z;
    int x0 = blockIdx.x * 32, y0 = blockIdx.y * 8;
    int warp = tid >> 5, lane = tid & 31;
    int wm = warp >> 1, wn = warp & 1;
    int lr = lane >> 2, lc = lane & 3;

    // ---- load input tile (channel-last bf16 hi|lo rows) ----
    {
        const __nv_bfloat16* src = g_hc + (size_t)b * HW * 128;
        for (int r0 = 0; r0 < ROWS; r0 += 16) {
            int row = r0 + (tid >> 4);
            if (row < ROWS) {
                int gy = y0 - R + row / TWX;
                int gx = x0 - R + row % TWX;
                uint4 v = make_uint4(0u, 0u, 0u, 0u);
                if (gy >= 0 && gy < 256 && gx >= 0 && gx < 256)
                    v = *(const uint4*)(src + ((size_t)gy * 256 + gx) * 128 + (tid & 15) * 8);
                *(uint4*)(tile + row * RB + (tid & 15) * 16) = v;
            }
        }
    }
    // ---- load tap-0 weights into buffer 0 ----
    {
        const uint4* src = (const uint4*)wc;
        int o = tid * 64, row = o >> 8, col = o & 255;
#pragma unroll
        for (int i = 0; i < 4; i++) {
            uint4 v = src[tid * 4 + i];
            *(uint4*)(wbuf + row * RB + col + i * 16) = v;
        }
    }
    __syncthreads();

    float d[4][4][4];
#pragma unroll
    for (int f = 0; f < 4; f++)
#pragma unroll
        for (int n = 0; n < 4; n++)
#pragma unroll
            for (int q = 0; q < 4; q++) d[f][n][q] = 0.f;

    for (int tap = 0; tap < K2; tap++) {
        int cur = tap & 1, nxt = cur ^ 1;
        // prefetch next tap weights into registers
        uint4 pv[4];
        bool more = (tap + 1 < K2);
        if (more) {
            const uint4* src = (const uint4*)(wc + (size_t)(tap + 1) * 64 * 128);
#pragma unroll
            for (int i = 0; i < 4; i++) pv[i] = src[tid * 4 + i];
        }
        int ky = tap / K, kx = tap % K;
        const char* wb = wbuf + cur * WB1;
        // per-frag A row base byte offsets for this tap
        int abase[4];
#pragma unroll
        for (int f = 0; f < 4; f++)
            abase[f] = (((wm * 2 + (f >> 1) + ky) * TWX) + ((f & 1) * 16) + lr + kx) * RB + lc * 8;

#pragma unroll
        for (int c = 0; c < 4; c++) {
            int co = c * 32;
            // A fragments: hi and lo
            uint2 AH0[4], AH1[4], AL0[4], AL1[4];
#pragma unroll
            for (int f = 0; f < 4; f++) {
                const char* p = tile + abase[f] + co;
                AH0[f] = *(const uint2*)p;
                AH1[f] = *(const uint2*)(p + 8 * RB);
                AL0[f] = *(const uint2*)(p + 128);
                AL1[f] = *(const uint2*)(p + 128 + 8 * RB);
            }
            // B fragments: hi and lo
            uint2 BH[4], BL[4];
#pragma unroll
            for (int n = 0; n < 4; n++) {
                const char* p = wb + (wn * 32 + n * 8 + lr) * RB + co + lc * 8;
                BH[n] = *(const uint2*)p;
                BL[n] = *(const uint2*)(p + 128);
            }
#pragma unroll
            for (int f = 0; f < 4; f++)
#pragma unroll
                for (int n = 0; n < 4; n++) {
                    mma_bf16(d[f][n], AH0[f].x, AH1[f].x, AH0[f].y, AH1[f].y, BH[n].x, BH[n].y);
                    mma_bf16(d[f][n], AH0[f].x, AH1[f].x, AH0[f].y, AH1[f].y, BL[n].x, BL[n].y);
                    mma_bf16(d[f][n], AL0[f].x, AL1[f].x, AL0[f].y, AL1[f].y, BH[n].x, BH[n].y);
                }
        }
        // stage prefetched weights into the other buffer
        if (more) {
            int o = tid * 64, row = o >> 8, col = o & 255;
#pragma unroll
            for (int i = 0; i < 4; i++)
                *(uint4*)(wbuf + nxt * WB1 + row * RB + col + i * 16) = pv[i];
        }
        __syncthreads();
    }

    // ---- epilogue: relu + planar store ----
#pragma unroll
    for (int f = 0; f < 4; f++) {
        int y = y0 + wm * 2 + (f >> 1);
        int x = x0 + (f & 1) * 16 + lr;
#pragma unroll
        for (int n = 0; n < 4; n++) {
            int oc = wn * 32 + n * 8 + lc * 2;
            float* o0 = out + ((size_t)(b * 192 + brBase + oc) * HW + y * 256 + x);
            o0[0]       = fmaxf(d[f][n][0], 0.f);
            o0[8]       = fmaxf(d[f][n][2], 0.f);
            o0[HW]      = fmaxf(d[f][n][1], 0.f);
            o0[HW + 8]  = fmaxf(d[f][n][3], 0.f);
        }
    }
}

// ---------------- BN stats ----------------
__global__ void k_bnsum() {
    int c = blockIdx.x >> 2, seg = blockIdx.x & 3, tid = threadIdx.x;
    int base = seg * 32768;
    double s[4] = {0, 0, 0, 0}, s2[4] = {0, 0, 0, 0};
    for (int u = 0; u < 32; u++) {
        int t = base + u * 1024 + tid * 4;
#pragma unroll
        for (int q = 0; q < 4; q++) {
            int tt = t + q;
            int bb = tt >> 16, p = tt & (HW - 1);
            float v = g_m64[(size_t)(bb * 64 + c) * HW + p];
            s[q] += v; s2[q] += (double)v * v;
        }
    }
    double ss = (s[0] + s[1]) + (s[2] + s[3]);
    double ss2 = (s2[0] + s2[1]) + (s2[2] + s2[3]);
    __shared__ double sh1[256], sh2[256];
    sh1[tid] = ss; sh2[tid] = ss2; __syncthreads();
    for (int st = 128; st > 0; st >>= 1) {
        if (tid < st) { sh1[tid] += sh1[tid + st]; sh2[tid] += sh2[tid + st]; }
        __syncthreads();
    }
    if (tid == 0) { g_ps1[c][seg] = sh1[0]; g_ps2[c][seg] = sh2[0]; }
}

__global__ void k_bncoef(const float* __restrict__ bn_g, const float* __restrict__ bn_b) {
    int c = threadIdx.x;
    double N = (double)(Bn * HW);
    double s1 = (g_ps1[c][0] + g_ps1[c][1]) + (g_ps1[c][2] + g_ps1[c][3]);
    double s2 = (g_ps2[c][0] + g_ps2[c][1]) + (g_ps2[c][2] + g_ps2[c][3]);
    double mean = s1 / N;
    double var = s2 / N - mean * mean;
    float a = (float)((double)bn_g[c] / sqrt(var + 1e-5));
    g_a[c] = a;
    g_bc[c] = bn_b[c] - (float)mean * a;
}

__global__ void k_ymean() {
    int c = blockIdx.x, b = blockIdx.y, tid = threadIdx.x;
    float a = g_a[c], bc = g_bc[c];
    const float* mp = g_m64 + (size_t)(b * 64 + c) * HW;
    double s[4] = {0, 0, 0, 0};
    for (int p = tid * 4; p < HW; p += 1024) {
#pragma unroll
        for (int q = 0; q < 4; q++)
            s[q] += (double)fmaxf(fmaf(a, mp[p + q], bc), 0.f);
    }
    __shared__ double sh[256];
    sh[tid] = (s[0] + s[1]) + (s[2] + s[3]); __syncthreads();
    for (int st = 128; st > 0; st >>= 1) {
        if (tid < st) sh[tid] += sh[tid + st];
        __syncthreads();
    }
    if (tid == 0) g_ym[b * 64 + c] = sh[0] / (double)HW;
}

__global__ void k_se(const float* __restrict__ se1, const float* __restrict__ se2) {
    __shared__ float t1[2][4];
    int tid = threadIdx.x;
    for (int b = 0; b < 2; b++) {
        if (tid < 4) {
            float s = 0.f;
            for (int c = 0; c < 64; c++) s += se1[tid * 64 + c] * (float)g_ym[b * 64 + c];
            t1[b][tid] = fmaxf(s, 0.f);
        }
    }
    __syncthreads();
    for (int b = 0; b < 2; b++) {
        float z = 0.f;
        for (int j = 0; j < 4; j++) z += se2[tid * 4 + j] * t1[b][j];
        g_y[b * 64 + tid] = 1.f / (1.f + expf(-z));
    }
}

__global__ void k_final(const float* __restrict__ wf, float* __restrict__ out) {
    __shared__ float wy[576], sa[64], sb[64];
    int b = blockIdx.y;
    int tid = threadIdx.x;
    for (int t = tid; t < 576; t += 256) {
        int c = t / 9;
        wy[t] = __ldg(&wf[t]) * g_y[b * 64 + c];
    }
    if (tid < 64) { sa[tid] = g_a[tid]; sb[tid] = g_bc[tid]; }
    __syncthreads();
    int bx = blockIdx.x;
    int tx0 = (bx & 15) * 16, ty0 = (bx >> 4) * 16;
    int i = ty0 + (tid >> 4), j = tx0 + (tid & 15);
    float acc = 0.f;
    const float* mb = g_m64 + (size_t)b * 64 * HW;
    for (int c = 0; c < 64; c++) {
        float a = sa[c], bc = sb[c];
        const float* mc = mb + (size_t)c * HW;
#pragma unroll
        for (int ky = 0; ky < 3; ky++) {
            int yy = i + ky - 1; if (yy < 0 || yy > 255) continue;
#pragma unroll
            for (int kx = 0; kx < 3; kx++) {
                int xx = j + kx - 1; if (xx < 0 || xx > 255) continue;
                float v = __ldg(&mc[yy * 256 + xx]);
                float t = fmaxf(fmaf(a, v, bc), 0.f);
                acc = fmaf(wy[c * 9 + ky * 3 + kx], t, acc);
            }
        }
    }
    int p = i * 256 + j;
    out[b * HW + p] = g_xp[b * HW + p] - acc;
}

// ---------------- launch ----------------
extern "C" void kernel_launch(void* const* d_in, const int* in_sizes, int n_in,
                              void* d_out, int out_size) {
    const float* x    = (const float*)d_in[0];
    const float* w_i3 = (const float*)d_in[1];
    const float* w_i5 = (const float*)d_in[2];
    const float* w_i7 = (const float*)d_in[3];
    const float* w_p1 = (const float*)d_in[4];
    const float* wb3  = (const float*)d_in[5];
    const float* wb5  = (const float*)d_in[6];
    const float* wb7  = (const float*)d_in[7];
    const float* wbp  = (const float*)d_in[8];
    const float* bn_g = (const float*)d_in[9];
    const float* bn_b = (const float*)d_in[10];
    const float* se1  = (const float*)d_in[11];
    const float* se2  = (const float*)d_in[12];
    const float* wf   = (const float*)d_in[13];
    float* out = (float*)d_out;

    float *xp, *h192, *h64, *m192, *m64;
    cudaGetSymbolAddress((void**)&xp,   g_xp);
    cudaGetSymbolAddress((void**)&h192, g_h192);
    cudaGetSymbolAddress((void**)&h64,  g_h64);
    cudaGetSymbolAddress((void**)&m192, g_m192);
    cudaGetSymbolAddress((void**)&m64,  g_m64);
    __nv_bfloat16 *wc3, *wc5, *wc7;
    cudaGetSymbolAddress((void**)&wc3, g_wc3);
    cudaGetSymbolAddress((void**)&wc5, g_wc5);
    cudaGetSymbolAddress((void**)&wc7, g_wc7);

    // dynamic smem sizes for mconv
    const int smem1 = (34 * 10) * 272 + 2 * 64 * 272;   // R=1: 127296
    const int smem2 = (36 * 12) * 272 + 2 * 64 * 272;   // R=2: 152320
    const int smem3 = (38 * 14) * 272 + 2 * 64 * 272;   // R=3: 179520
    cudaFuncSetAttribute(k_mconv<1>, cudaFuncAttributeMaxDynamicSharedMemorySize, smem1);
    cudaFuncSetAttribute(k_mconv<2>, cudaFuncAttributeMaxDynamicSharedMemorySize, smem2);
    cudaFuncSetAttribute(k_mconv<3>, cudaFuncAttributeMaxDynamicSharedMemorySize, smem3);

    k_pre<<<512, 256>>>(x);

    dim3 g1(128, Bn * 8);   // 128 tiles of 32x16, (b,ocg of 8)
    k_conv1<1><<<g1, 128>>>(xp, w_i3, h192, 0);
    k_conv1<2><<<g1, 128>>>(xp, w_i5, h192, 64);
    k_conv1<3><<<g1, 128>>>(xp, w_i7, h192, 128);

    k_1x1<<<dim3(128, 4), 256>>>(h192, w_p1, h64);

    // convert h64 to channel-last bf16 hi/lo + weights
    k_tr<<<dim3(HW / 64, Bn), 256>>>(h64);
    k_wc<<<dim3(16, 9),  256>>>(wb3, wc3);
    k_wc<<<dim3(16, 25), 256>>>(wb5, wc5);
    k_wc<<<dim3(16, 49), 256>>>(wb7, wc7);

    dim3 gm(8, 32, Bn);
    k_mconv<1><<<gm, 256, smem1>>>(wc3, m192, 0);
    k_mconv<2><<<gm, 256, smem2>>>(wc5, m192, 64);
    k_mconv<3><<<gm, 256, smem3>>>(wc7, m192, 128);

    k_1x1<<<dim3(128, 4), 256>>>(m192, wbp, m64);

    k_bnsum<<<256, 256>>>();
    k_bncoef<<<1, 64>>>(bn_g, bn_b);
    k_ymean<<<dim3(64, 2), 256>>>();
    k_se<<<1, 64>>>(se1, se2);
    k_final<<<dim3(256, 2), 256>>>(wf, out);
}

// round 8
// speedup vs baseline: 2.8489x; 1.2322x over previous
#include <cuda_runtime.h>
#include <cuda_bf16.h>
#include <math.h>

#define HW 65536
#define Bn 2

// ---------------- scratch ----------------
__device__ float g_xp[Bn * HW];
__device__ float g_h192[Bn * 192 * HW];
__device__ float g_m192[Bn * 192 * HW];
__device__ float g_m64[Bn * 64 * HW];
__device__ double g_ps1[64][4], g_ps2[64][4];
__device__ float g_a[64], g_bc[64];
__device__ double g_ym[Bn * 64];
__device__ float g_y[Bn * 64];
// channel-last bf16 hi|lo input for mid convs: [b][px][128]
__device__ __nv_bfloat16 g_hc[(size_t)Bn * HW * 128];
// per-tap weights, rows [oc][hi 64 | lo 64] bf16 (permuted ic order)
__device__ __nv_bfloat16 g_wc3[9 * 64 * 128];
__device__ __nv_bfloat16 g_wc5[25 * 64 * 128];
__device__ __nv_bfloat16 g_wc7[49 * 64 * 128];

// permuted within-16 element index (k-pair interleave so LDS.64 = (k01,k89) frag regs)
__device__ __host__ __forceinline__ int permCol(int ic) {
    int jj = ic & 15, q = jj >> 1, e = jj & 1;
    int sp = (q < 4) ? 2 * q : 2 * (q - 4) + 1;
    return (ic & ~15) + 2 * sp + e;
}

// ---------------- preprocess ----------------
__device__ __forceinline__ float blendf(float v) {
    float g = fminf(fmaxf((v + 1.0f) * 0.5f, 1e-6f), 1.0f);
    return 0.6f * g + 0.4f * g * sqrtf(g);
}

__global__ void k_pre(const float* __restrict__ x) {
    int idx = blockIdx.x * blockDim.x + threadIdx.x;
    if (idx >= Bn * HW) return;
    int b = idx >> 16, p = idx & (HW - 1);
    int i = p >> 8, j = p & 255;
    const float* xb = x + b * HW;
    float c = blendf(xb[p]);
    const int   di[13] = {-2,-1,-1,-1, 0, 0, 0, 0, 0, 1, 1, 1, 2};
    const int   dj[13] = { 0,-1, 0, 1,-2,-1, 0, 1, 2,-1, 0, 1, 0};
    const float sw[13] = {0.99920032f,0.99960008f,0.99980002f,0.99960008f,
                          0.99920032f,0.99980002f,1.0f,0.99980002f,0.99920032f,
                          0.99960008f,0.99980002f,0.99960008f,0.99920032f};
    float num = 0.f, den = 0.f;
#pragma unroll
    for (int t = 0; t < 13; t++) {
        int ri = i + di[t]; ri = ri < 0 ? -ri : (ri > 255 ? 510 - ri : ri);
        int rj = j + dj[t]; rj = rj < 0 ? -rj : (rj > 255 ? 510 - rj : rj);
        float sh = blendf(xb[ri * 256 + rj]);
        float d = sh - c;
        float w = sw[t] * expf(-200.0f * d * d);
        num = fmaf(w, sh, num);
        den += w;
    }
    g_xp[idx] = num / den;
}

// ---------------- KxK conv for IC=1 (input convs), scalar fp32 ----------------
template<int R>
__global__ void k_conv1(const float* __restrict__ in, const float* __restrict__ w,
                        float* __restrict__ out, int brBase) {
    constexpr int K = 2 * R + 1, K2 = K * K;
    constexpr int TW = 32 + 2 * R, TH = 16 + 2 * R;
    __shared__ float tile[TH * TW];
    __shared__ float ws[8 * K2];
    int bx = blockIdx.x;
    int tx0 = (bx & 7) * 32, ty0 = (bx >> 3) * 16;
    int b = blockIdx.y >> 3, ocg = blockIdx.y & 7;
    int oc0 = ocg * 8;
    int tid = threadIdx.x;            // 128
    int row = tid >> 3, xq = (tid & 7) * 4;
    const float* icp = in + (size_t)b * HW;
    for (int t = tid; t < TH * TW; t += 128) {
        int yy = ty0 - R + t / TW, xx = tx0 - R + t % TW;
        tile[t] = (yy >= 0 && yy < 256 && xx >= 0 && xx < 256)
                ? __ldg(&icp[yy * 256 + xx]) : 0.f;
    }
    for (int t = tid; t < 8 * K2; t += 128) {
        int o = t / K2;
        ws[t] = w[(size_t)(oc0 + o) * K2 + (t - o * K2)];
    }
    __syncthreads();
    float acc[8][4];
#pragma unroll
    for (int o = 0; o < 8; o++)
#pragma unroll
        for (int q = 0; q < 4; q++) acc[o][q] = 0.f;
#pragma unroll
    for (int ky = 0; ky < K; ky++) {
#pragma unroll
        for (int kx = 0; kx < K; kx++) {
            int base = (row + ky) * TW + xq + kx;
            float t0 = tile[base], t1 = tile[base + 1];
            float t2 = tile[base + 2], t3 = tile[base + 3];
#pragma unroll
            for (int o = 0; o < 8; o++) {
                float wv = ws[o * K2 + ky * K + kx];
                acc[o][0] = fmaf(t0, wv, acc[o][0]);
                acc[o][1] = fmaf(t1, wv, acc[o][1]);
                acc[o][2] = fmaf(t2, wv, acc[o][2]);
                acc[o][3] = fmaf(t3, wv, acc[o][3]);
            }
        }
    }
    size_t ob = (size_t)(b * 192 + brBase + oc0) * HW + (ty0 + row) * 256 + tx0 + xq;
#pragma unroll
    for (int o = 0; o < 8; o++)
#pragma unroll
        for (int q = 0; q < 4; q++)
            out[ob + (size_t)o * HW + q] = fmaxf(acc[o][q], 0.f);
}

// ---------------- bf16 mma helper ----------------
__device__ __forceinline__ void mma_bf16(float* d, unsigned a0, unsigned a1,
                                         unsigned a2, unsigned a3,
                                         unsigned b0, unsigned b1) {
    asm("mma.sync.aligned.m16n8k16.row.col.f32.bf16.bf16.f32 "
        "{%0,%1,%2,%3},{%4,%5,%6,%7},{%8,%9},{%0,%1,%2,%3};"
        : "+f"(d[0]), "+f"(d[1]), "+f"(d[2]), "+f"(d[3])
        : "r"(a0), "r"(a1), "r"(a2), "r"(a3), "r"(b0), "r"(b1));
}

// hi/lo split + pack two values into bf16x2 words
__device__ __forceinline__ unsigned packhl(float a, float b, unsigned& lo) {
    __nv_bfloat16 ha = __float2bfloat16_rn(a);
    __nv_bfloat16 hb = __float2bfloat16_rn(b);
    float la = a - __bfloat162float(ha);
    float lb = b - __bfloat162float(hb);
    __nv_bfloat162 l2 = __float22bfloat162_rn(make_float2(la, lb));
    lo = *reinterpret_cast<unsigned*>(&l2);
    __nv_bfloat162 h2; h2.x = ha; h2.y = hb;
    return *reinterpret_cast<unsigned*>(&h2);
}

// ---------------- planar 1x1 conv via tensor cores: 192 -> 64 ----------------
// CTA 256 thr: 256 px, all 64 oc. Warp w owns px [w*32, w*32+32).
// A = W[64][192] (smem, bf16 hi/lo), B = X[ic][px] planar fp32, staged per
// 16-ic chunk as k-pair-interleaved bf16 hi/lo.
// EPI 0: write channel-last bf16 hi|lo (g_hc format). EPI 1: planar fp32.
// Epilogue staging rows are 272 B (16B-aligned!) — 264 traps LDS.128.
template<int EPI>
__global__ void __launch_bounds__(256) k_p1x1(
        const float* __restrict__ in, const float* __restrict__ w,
        float* __restrict__ outPlanar, __nv_bfloat16* __restrict__ outCL) {
    // smem: [0,25600) wsmH 64x400 | [25600,51200) wsmL | [51200,59520) bsmH 8x1040
    //       [59520,67840) bsmL.  Epilogue staging reuses [0, 8*8704).
    extern __shared__ char sm[];
    char* wsmH = sm;
    char* wsmL = sm + 25600;
    char* bsmH = sm + 51200;
    char* bsmL = sm + 59520;

    int tid = threadIdx.x;
    int b = blockIdx.y;
    int px0 = blockIdx.x * 256;
    int warp = tid >> 5, lane = tid & 31;
    int lr = lane >> 2, lc = lane & 3;
    int kp = warp;               // staging k-pair row (0..7)
    int px8 = lane * 8;          // staging px offset
    int pxw = warp * 32;         // mma warp px base

    const float* X = in + (size_t)b * 192 * HW + px0;

    // ---- load weights, split hi/lo ----
    {
        int oc = tid >> 2, seg = tid & 3;
        const float* wr = w + oc * 192 + seg * 48;
        __nv_bfloat16* dh = (__nv_bfloat16*)(wsmH + oc * 400) + seg * 48;
        __nv_bfloat16* dl = (__nv_bfloat16*)(wsmL + oc * 400) + seg * 48;
        for (int i = 0; i < 48; i++) {
            float v = __ldg(&wr[i]);
            __nv_bfloat16 h = __float2bfloat16_rn(v);
            dh[i] = h;
            dl[i] = __float2bfloat16_rn(v - __bfloat162float(h));
        }
    }
    // ---- stage chunk 0 ----
    {
        const float* r0 = X + (size_t)(2 * kp) * HW + px8;
        const float* r1 = r0 + HW;
        float4 p0 = *(const float4*)r0, p1 = *(const float4*)(r0 + 4);
        float4 p2 = *(const float4*)r1, p3 = *(const float4*)(r1 + 4);
        uint4 H0, L0, H1, L1;
        H0.x = packhl(p0.x, p2.x, L0.x); H0.y = packhl(p0.y, p2.y, L0.y);
        H0.z = packhl(p0.z, p2.z, L0.z); H0.w = packhl(p0.w, p2.w, L0.w);
        H1.x = packhl(p1.x, p3.x, L1.x); H1.y = packhl(p1.y, p3.y, L1.y);
        H1.z = packhl(p1.z, p3.z, L1.z); H1.w = packhl(p1.w, p3.w, L1.w);
        *(uint4*)(bsmH + kp * 1040 + lane * 32) = H0;
        *(uint4*)(bsmH + kp * 1040 + lane * 32 + 16) = H1;
        *(uint4*)(bsmL + kp * 1040 + lane * 32) = L0;
        *(uint4*)(bsmL + kp * 1040 + lane * 32 + 16) = L1;
    }
    __syncthreads();

    float d[4][4][4];
#pragma unroll
    for (int mf = 0; mf < 4; mf++)
#pragma unroll
        for (int nf = 0; nf < 4; nf++)
#pragma unroll
            for (int q = 0; q < 4; q++) d[mf][nf][q] = 0.f;

    for (int c = 0; c < 12; c++) {
        // prefetch next chunk
        float4 p0, p1, p2, p3;
        bool more = (c < 11);
        if (more) {
            const float* r0 = X + (size_t)((c + 1) * 16 + 2 * kp) * HW + px8;
            const float* r1 = r0 + HW;
            p0 = *(const float4*)r0; p1 = *(const float4*)(r0 + 4);
            p2 = *(const float4*)r1; p3 = *(const float4*)(r1 + 4);
        }
        // B fragments
        unsigned BH0[4], BH1[4], BL0[4], BL1[4];
#pragma unroll
        for (int nf = 0; nf < 4; nf++) {
            int col = (pxw + nf * 8 + lr) * 4;
            const char* ph = bsmH + lc * 1040 + col;
            const char* pl = bsmL + lc * 1040 + col;
            BH0[nf] = *(const unsigned*)ph;
            BH1[nf] = *(const unsigned*)(ph + 4 * 1040);
            BL0[nf] = *(const unsigned*)pl;
            BL1[nf] = *(const unsigned*)(pl + 4 * 1040);
        }
        // A fragments + mma
#pragma unroll
        for (int mf = 0; mf < 4; mf++) {
            const char* ah = wsmH + (mf * 16 + lr) * 400 + c * 32 + lc * 4;
            const char* al = wsmL + (mf * 16 + lr) * 400 + c * 32 + lc * 4;
            unsigned AH0 = *(const unsigned*)ah;
            unsigned AH1 = *(const unsigned*)(ah + 8 * 400);
            unsigned AH2 = *(const unsigned*)(ah + 16);
            unsigned AH3 = *(const unsigned*)(ah + 8 * 400 + 16);
            unsigned AL0 = *(const unsigned*)al;
            unsigned AL1 = *(const unsigned*)(al + 8 * 400);
            unsigned AL2 = *(const unsigned*)(al + 16);
            unsigned AL3 = *(const unsigned*)(al + 8 * 400 + 16);
#pragma unroll
            for (int nf = 0; nf < 4; nf++) {
                mma_bf16(d[mf][nf], AH0, AH1, AH2, AH3, BH0[nf], BH1[nf]);
                mma_bf16(d[mf][nf], AH0, AH1, AH2, AH3, BL0[nf], BL1[nf]);
                mma_bf16(d[mf][nf], AL0, AL1, AL2, AL3, BH0[nf], BH1[nf]);
            }
        }
        __syncthreads();
        if (more) {
            uint4 H0, L0, H1, L1;
            H0.x = packhl(p0.x, p2.x, L0.x); H0.y = packhl(p0.y, p2.y, L0.y);
            H0.z = packhl(p0.z, p2.z, L0.z); H0.w = packhl(p0.w, p2.w, L0.w);
            H1.x = packhl(p1.x, p3.x, L1.x); H1.y = packhl(p1.y, p3.y, L1.y);
            H1.z = packhl(p1.z, p3.z, L1.z); H1.w = packhl(p1.w, p3.w, L1.w);
            *(uint4*)(bsmH + kp * 1040 + lane * 32) = H0;
            *(uint4*)(bsmH + kp * 1040 + lane * 32 + 16) = H1;
            *(uint4*)(bsmL + kp * 1040 + lane * 32) = L0;
            *(uint4*)(bsmL + kp * 1040 + lane * 32 + 16) = L1;
        }
        __syncthreads();
    }

    if (EPI == 1) {
        // planar fp32 store
#pragma unroll
        for (int mf = 0; mf < 4; mf++) {
            int oc = mf * 16 + lr;
#pragma unroll
            for (int nf = 0; nf < 4; nf++) {
                int px = px0 + pxw + nf * 8 + 2 * lc;
                *(float2*)&outPlanar[(size_t)(b * 64 + oc) * HW + px] =
                    make_float2(d[mf][nf][0], d[mf][nf][1]);
                *(float2*)&outPlanar[(size_t)(b * 64 + oc + 8) * HW + px] =
                    make_float2(d[mf][nf][2], d[mf][nf][3]);
            }
        }
    } else {
        // channel-last bf16 hi|lo via smem staging (g_hc format, permCol)
        char* est = sm + warp * 8704;   // [32 px][272 B rows, 16B-aligned]
#pragma unroll
        for (int mf = 0; mf < 4; mf++) {
            int col0 = permCol(mf * 16 + lr);
            int col8 = permCol(mf * 16 + lr + 8);
#pragma unroll
            for (int nf = 0; nf < 4; nf++) {
                int pxl = nf * 8 + 2 * lc;
#pragma unroll
                for (int e = 0; e < 2; e++) {
                    {
                        float v = d[mf][nf][e];
                        __nv_bfloat16 h = __float2bfloat16_rn(v);
                        *(__nv_bfloat16*)(est + (pxl + e) * 272 + col0 * 2) = h;
                        *(__nv_bfloat16*)(est + (pxl + e) * 272 + (64 + col0) * 2) =
                            __float2bfloat16_rn(v - __bfloat162float(h));
                    }
                    {
                        float v = d[mf][nf][2 + e];
                        __nv_bfloat16 h = __float2bfloat16_rn(v);
                        *(__nv_bfloat16*)(est + (pxl + e) * 272 + col8 * 2) = h;
                        *(__nv_bfloat16*)(est + (pxl + e) * 272 + (64 + col8) * 2) =
                            __float2bfloat16_rn(v - __bfloat162float(h));
                    }
                }
            }
        }
        __syncthreads();
#pragma unroll
        for (int r = 0; r < 16; r++) {
            int pxl = r * 2 + (lane >> 4);
            int ch = lane & 15;
            uint4 v = *(const uint4*)(sm + warp * 8704 + pxl * 272 + ch * 16);
            *(uint4*)((char*)outCL + ((size_t)b * HW + px0 + pxw + pxl) * 256 + ch * 16) = v;
        }
    }
}

// ---------------- weight convert: [oc][ic][K2] fp32 -> per-tap bf16 hi|lo rows ----
__global__ void k_wc(const float* __restrict__ w, __nv_bfloat16* __restrict__ wc) {
    int tap = blockIdx.y;
    int K2 = gridDim.y;
    int t = blockIdx.x * 256 + threadIdx.x;   // 0..4095
    int oc = t >> 6, ic = t & 63;
    float v = w[((size_t)oc * 64 + ic) * K2 + tap];
    __nv_bfloat16 hi = __float2bfloat16_rn(v);
    float lo = v - __bfloat162float(hi);
    __nv_bfloat16* row = wc + ((size_t)tap * 64 + oc) * 128;
    int col = permCol(ic);
    row[col] = hi;
    row[64 + col] = __float2bfloat16_rn(lo);
}

// ---------------- mid conv: 64->64, KxK, tensor-core bf16 hi/lo ----------------
template<int R>
__global__ void __launch_bounds__(256) k_mconv(
        const __nv_bfloat16* __restrict__ wc,
        float* __restrict__ out, int brBase) {
    constexpr int K = 2 * R + 1, K2 = K * K;
    constexpr int TWX = 32 + 2 * R, TWY = 8 + 2 * R, ROWS = TWX * TWY;
    constexpr int RB = 272;
    constexpr int WB1 = 64 * 272;
    extern __shared__ char smem[];
    char* tile = smem;
    char* wbuf = smem + ROWS * RB;

    int tid = threadIdx.x;
    int b = blockIdx.z;
    int x0 = blockIdx.x * 32, y0 = blockIdx.y * 8;
    int warp = tid >> 5, lane = tid & 31;
    int wm = warp >> 1, wn = warp & 1;
    int lr = lane >> 2, lc = lane & 3;

    {
        const __nv_bfloat16* src = g_hc + (size_t)b * HW * 128;
        for (int r0 = 0; r0 < ROWS; r0 += 16) {
            int row = r0 + (tid >> 4);
            if (row < ROWS) {
                int gy = y0 - R + row / TWX;
                int gx = x0 - R + row % TWX;
                uint4 v = make_uint4(0u, 0u, 0u, 0u);
                if (gy >= 0 && gy < 256 && gx >= 0 && gx < 256)
                    v = *(const uint4*)(src + ((size_t)gy * 256 + gx) * 128 + (tid & 15) * 8);
                *(uint4*)(tile + row * RB + (tid & 15) * 16) = v;
            }
        }
    }
    {
        const uint4* src = (const uint4*)wc;
        int o = tid * 64, row = o >> 8, col = o & 255;
#pragma unroll
        for (int i = 0; i < 4; i++) {
            uint4 v = src[tid * 4 + i];
            *(uint4*)(wbuf + row * RB + col + i * 16) = v;
        }
    }
    __syncthreads();

    float d[4][4][4];
#pragma unroll
    for (int f = 0; f < 4; f++)
#pragma unroll
        for (int n = 0; n < 4; n++)
#pragma unroll
            for (int q = 0; q < 4; q++) d[f][n][q] = 0.f;

    for (int tap = 0; tap < K2; tap++) {
        int cur = tap & 1, nxt = cur ^ 1;
        uint4 pv[4];
        bool more = (tap + 1 < K2);
        if (more) {
            const uint4* src = (const uint4*)(wc + (size_t)(tap + 1) * 64 * 128);
#pragma unroll
            for (int i = 0; i < 4; i++) pv[i] = src[tid * 4 + i];
        }
        int ky = tap / K, kx = tap % K;
        const char* wb = wbuf + cur * WB1;
        int abase[4];
#pragma unroll
        for (int f = 0; f < 4; f++)
            abase[f] = (((wm * 2 + (f >> 1) + ky) * TWX) + ((f & 1) * 16) + lr + kx) * RB + lc * 8;

#pragma unroll
        for (int c = 0; c < 4; c++) {
            int co = c * 32;
            uint2 AH0[4], AH1[4], AL0[4], AL1[4];
#pragma unroll
            for (int f = 0; f < 4; f++) {
                const char* p = tile + abase[f] + co;
                AH0[f] = *(const uint2*)p;
                AH1[f] = *(const uint2*)(p + 8 * RB);
                AL0[f] = *(const uint2*)(p + 128);
                AL1[f] = *(const uint2*)(p + 128 + 8 * RB);
            }
            uint2 BH[4], BL[4];
#pragma unroll
            for (int n = 0; n < 4; n++) {
                const char* p = wb + (wn * 32 + n * 8 + lr) * RB + co + lc * 8;
                BH[n] = *(const uint2*)p;
                BL[n] = *(const uint2*)(p + 128);
            }
#pragma unroll
            for (int f = 0; f < 4; f++)
#pragma unroll
                for (int n = 0; n < 4; n++) {
                    mma_bf16(d[f][n], AH0[f].x, AH1[f].x, AH0[f].y, AH1[f].y, BH[n].x, BH[n].y);
                    mma_bf16(d[f][n], AH0[f].x, AH1[f].x, AH0[f].y, AH1[f].y, BL[n].x, BL[n].y);
                    mma_bf16(d[f][n], AL0[f].x, AL1[f].x, AL0[f].y, AL1[f].y, BH[n].x, BH[n].y);
                }
        }
        if (more) {
            int o = tid * 64, row = o >> 8, col = o & 255;
#pragma unroll
            for (int i = 0; i < 4; i++)
                *(uint4*)(wbuf + nxt * WB1 + row * RB + col + i * 16) = pv[i];
        }
        __syncthreads();
    }

#pragma unroll
    for (int f = 0; f < 4; f++) {
        int y = y0 + wm * 2 + (f >> 1);
        int x = x0 + (f & 1) * 16 + lr;
#pragma unroll
        for (int n = 0; n < 4; n++) {
            int oc = wn * 32 + n * 8 + lc * 2;
            float* o0 = out + ((size_t)(b * 192 + brBase + oc) * HW + y * 256 + x);
            o0[0]       = fmaxf(d[f][n][0], 0.f);
            o0[8]       = fmaxf(d[f][n][2], 0.f);
            o0[HW]      = fmaxf(d[f][n][1], 0.f);
            o0[HW + 8]  = fmaxf(d[f][n][3], 0.f);
        }
    }
}

// ---------------- BN stats ----------------
__global__ void k_bnsum() {
    int c = blockIdx.x >> 2, seg = blockIdx.x & 3, tid = threadIdx.x;
    int base = seg * 32768;
    double s[4] = {0, 0, 0, 0}, s2[4] = {0, 0, 0, 0};
    for (int u = 0; u < 32; u++) {
        int t = base + u * 1024 + tid * 4;
#pragma unroll
        for (int q = 0; q < 4; q++) {
            int tt = t + q;
            int bb = tt >> 16, p = tt & (HW - 1);
            float v = g_m64[(size_t)(bb * 64 + c) * HW + p];
            s[q] += v; s2[q] += (double)v * v;
        }
    }
    double ss = (s[0] + s[1]) + (s[2] + s[3]);
    double ss2 = (s2[0] + s2[1]) + (s2[2] + s2[3]);
    __shared__ double sh1[256], sh2[256];
    sh1[tid] = ss; sh2[tid] = ss2; __syncthreads();
    for (int st = 128; st > 0; st >>= 1) {
        if (tid < st) { sh1[tid] += sh1[tid + st]; sh2[tid] += sh2[tid + st]; }
        __syncthreads();
    }
    if (tid == 0) { g_ps1[c][seg] = sh1[0]; g_ps2[c][seg] = sh2[0]; }
}

__global__ void k_bncoef(const float* __restrict__ bn_g, const float* __restrict__ bn_b) {
    int c = threadIdx.x;
    double N = (double)(Bn * HW);
    double s1 = (g_ps1[c][0] + g_ps1[c][1]) + (g_ps1[c][2] + g_ps1[c][3]);
    double s2 = (g_ps2[c][0] + g_ps2[c][1]) + (g_ps2[c][2] + g_ps2[c][3]);
    double mean = s1 / N;
    double var = s2 / N - mean * mean;
    float a = (float)((double)bn_g[c] / sqrt(var + 1e-5));
    g_a[c] = a;
    g_bc[c] = bn_b[c] - (float)mean * a;
}

__global__ void k_ymean() {
    int c = blockIdx.x, b = blockIdx.y, tid = threadIdx.x;
    float a = g_a[c], bc = g_bc[c];
    const float* mp = g_m64 + (size_t)(b * 64 + c) * HW;
    double s[4] = {0, 0, 0, 0};
    for (int p = tid * 4; p < HW; p += 1024) {
#pragma unroll
        for (int q = 0; q < 4; q++)
            s[q] += (double)fmaxf(fmaf(a, mp[p + q], bc), 0.f);
    }
    __shared__ double sh[256];
    sh[tid] = (s[0] + s[1]) + (s[2] + s[3]); __syncthreads();
    for (int st = 128; st > 0; st >>= 1) {
        if (tid < st) sh[tid] += sh[tid + st];
        __syncthreads();
    }
    if (tid == 0) g_ym[b * 64 + c] = sh[0] / (double)HW;
}

__global__ void k_se(const float* __restrict__ se1, const float* __restrict__ se2) {
    __shared__ float t1[2][4];
    int tid = threadIdx.x;
    for (int b = 0; b < 2; b++) {
        if (tid < 4) {
            float s = 0.f;
            for (int c = 0; c < 64; c++) s += se1[tid * 64 + c] * (float)g_ym[b * 64 + c];
            t1[b][tid] = fmaxf(s, 0.f);
        }
    }
    __syncthreads();
    for (int b = 0; b < 2; b++) {
        float z = 0.f;
        for (int j = 0; j < 4; j++) z += se2[tid * 4 + j] * t1[b][j];
        g_y[b * 64 + tid] = 1.f / (1.f + expf(-z));
    }
}

__global__ void k_final(const float* __restrict__ wf, float* __restrict__ out) {
    __shared__ float wy[576], sa[64], sb[64];
    int b = blockIdx.y;
    int tid = threadIdx.x;
    for (int t = tid; t < 576; t += 256) {
        int c = t / 9;
        wy[t] = __ldg(&wf[t]) * g_y[b * 64 + c];
    }
    if (tid < 64) { sa[tid] = g_a[tid]; sb[tid] = g_bc[tid]; }
    __syncthreads();
    int bx = blockIdx.x;
    int tx0 = (bx & 15) * 16, ty0 = (bx >> 4) * 16;
    int i = ty0 + (tid >> 4), j = tx0 + (tid & 15);
    float acc = 0.f;
    const float* mb = g_m64 + (size_t)b * 64 * HW;
    for (int c = 0; c < 64; c++) {
        float a = sa[c], bc = sb[c];
        const float* mc = mb + (size_t)c * HW;
#pragma unroll
        for (int ky = 0; ky < 3; ky++) {
            int yy = i + ky - 1; if (yy < 0 || yy > 255) continue;
#pragma unroll
            for (int kx = 0; kx < 3; kx++) {
                int xx = j + kx - 1; if (xx < 0 || xx > 255) continue;
                float v = __ldg(&mc[yy * 256 + xx]);
                float t = fmaxf(fmaf(a, v, bc), 0.f);
                acc = fmaf(wy[c * 9 + ky * 3 + kx], t, acc);
            }
        }
    }
    int p = i * 256 + j;
    out[b * HW + p] = g_xp[b * HW + p] - acc;
}

// ---------------- launch ----------------
extern "C" void kernel_launch(void* const* d_in, const int* in_sizes, int n_in,
                              void* d_out, int out_size) {
    const float* x    = (const float*)d_in[0];
    const float* w_i3 = (const float*)d_in[1];
    const float* w_i5 = (const float*)d_in[2];
    const float* w_i7 = (const float*)d_in[3];
    const float* w_p1 = (const float*)d_in[4];
    const float* wb3  = (const float*)d_in[5];
    const float* wb5  = (const float*)d_in[6];
    const float* wb7  = (const float*)d_in[7];
    const float* wbp  = (const float*)d_in[8];
    const float* bn_g = (const float*)d_in[9];
    const float* bn_b = (const float*)d_in[10];
    const float* se1  = (const float*)d_in[11];
    const float* se2  = (const float*)d_in[12];
    const float* wf   = (const float*)d_in[13];
    float* out = (float*)d_out;

    float *xp, *h192, *m192, *m64;
    cudaGetSymbolAddress((void**)&xp,   g_xp);
    cudaGetSymbolAddress((void**)&h192, g_h192);
    cudaGetSymbolAddress((void**)&m192, g_m192);
    cudaGetSymbolAddress((void**)&m64,  g_m64);
    __nv_bfloat16 *hc, *wc3, *wc5, *wc7;
    cudaGetSymbolAddress((void**)&hc,  g_hc);
    cudaGetSymbolAddress((void**)&wc3, g_wc3);
    cudaGetSymbolAddress((void**)&wc5, g_wc5);
    cudaGetSymbolAddress((void**)&wc7, g_wc7);

    const int smem1 = (34 * 10) * 272 + 2 * 64 * 272;
    const int smem2 = (36 * 12) * 272 + 2 * 64 * 272;
    const int smem3 = (38 * 14) * 272 + 2 * 64 * 272;
    const int smemP = 8 * 8704;   // 69632: epilogue staging is the max user
    cudaFuncSetAttribute(k_mconv<1>, cudaFuncAttributeMaxDynamicSharedMemorySize, smem1);
    cudaFuncSetAttribute(k_mconv<2>, cudaFuncAttributeMaxDynamicSharedMemorySize, smem2);
    cudaFuncSetAttribute(k_mconv<3>, cudaFuncAttributeMaxDynamicSharedMemorySize, smem3);
    cudaFuncSetAttribute(k_p1x1<0>, cudaFuncAttributeMaxDynamicSharedMemorySize, smemP);
    cudaFuncSetAttribute(k_p1x1<1>, cudaFuncAttributeMaxDynamicSharedMemorySize, smemP);

    k_pre<<<512, 256>>>(x);

    dim3 g1(128, Bn * 8);
    k_conv1<1><<<g1, 128>>>(xp, w_i3, h192, 0);
    k_conv1<2><<<g1, 128>>>(xp, w_i5, h192, 64);
    k_conv1<3><<<g1, 128>>>(xp, w_i7, h192, 128);

    k_p1x1<0><<<dim3(256, Bn), 256, smemP>>>(h192, w_p1, nullptr, hc);

    k_wc<<<dim3(16, 9),  256>>>(wb3, wc3);
    k_wc<<<dim3(16, 25), 256>>>(wb5, wc5);
    k_wc<<<dim3(16, 49), 256>>>(wb7, wc7);

    dim3 gm(8, 32, Bn);
    k_mconv<1><<<gm, 256, smem1>>>(wc3, m192, 0);
    k_mconv<2><<<gm, 256, smem2>>>(wc5, m192, 64);
    k_mconv<3><<<gm, 256, smem3>>>(wc7, m192, 128);

    k_p1x1<1><<<dim3(256, Bn), 256, smemP>>>(m192, wbp, m64, nullptr);

    k_bnsum<<<256, 256>>>();
    k_bncoef<<<1, 64>>>(bn_g, bn_b);
    k_ymean<<<dim3(64, 2), 256>>>();
    k_se<<<1, 64>>>(se1, se2);
    k_final<<<dim3(256, 2), 256>>>(wf, out);
}